// round 12
// baseline (speedup 1.0000x reference)
#include <cuda_runtime.h>
#include <cuda_fp16.h>
#include <cstdint>

#define BB   8
#define SS   4096
#define DD   1024
#define KK   128
#define MM   (BB * SS)
#define LN_EPS 1e-5f

// ---------------- scratch (static device arrays; no allocations) ----------------
__device__ float  g_beta   [ (size_t)MM * KK ];  // beta TRANSPOSED: (B,K,S) 16 MB
__device__ __half g_srseq_h[ (size_t)MM * KK ];  // (S,B,K) fp16, 8 MB
__device__ __half g_y_h    [ (size_t)MM * DD ];  // (S*B, D) fp16, 64 MB
__device__ __half g_wout_h [ (size_t)DD * KK ];  // W_out fp16

// ============================ helpers ============================
__device__ __forceinline__ uint32_t smem_u32(const void* p) {
    uint32_t a;
    asm("{ .reg .u64 t; cvta.to.shared.u64 t, %1; cvt.u32.u64 %0, t; }" : "=r"(a) : "l"(p));
    return a;
}
__device__ __forceinline__ void cp16(void* dst, const void* src) {
    uint32_t d = smem_u32(dst);
    asm volatile("cp.async.cg.shared.global [%0], [%1], 16;" :: "r"(d), "l"(src));
}
__device__ __forceinline__ uint32_t pkh2(float x, float y) {
    __half2 h = __floats2half2_rn(x, y);
    return *(uint32_t*)&h;
}
#define CP_COMMIT() asm volatile("cp.async.commit_group;" ::: "memory")
#define CP_WAIT1()  asm volatile("cp.async.wait_group 1;"  ::: "memory")

#define MMA_F16(c, a, b) \
    asm volatile("mma.sync.aligned.m16n8k16.row.col.f32.f16.f16.f32 " \
        "{%0,%1,%2,%3}, {%4,%5,%6,%7}, {%8,%9}, {%0,%1,%2,%3};" \
        : "+f"((c)[0]), "+f"((c)[1]), "+f"((c)[2]), "+f"((c)[3]) \
        : "r"((a)[0]), "r"((a)[1]), "r"((a)[2]), "r"((a)[3]), \
          "r"((b)[0]), "r"((b)[1]))

// ============================================================================
// GEMM1: beta^T = (x @ W_in^T)^T -> beta_t (B,K,S) fp32.
// fp16 MMA (m16n8k16, fp32 accum); operands stay fp32 in smem (cp.async),
// converted to half2 at fragment load (CVTs measured free, R5 vs R7).
// 256 thr = 8 warps, warp (wm,wn) owns 64x32; KC=32 (2 k16 steps); NSTG=2.
// ============================================================================
#define KC   32
#define SPAD 36
#define STG_F (128 * SPAD)
#define NSTG 2

__global__ __launch_bounds__(256, 2)
void gemm_beta(const float* __restrict__ A, const float* __restrict__ Bt)
{
    constexpr int KD = 1024;
    constexpr int NCH = KD / KC;
    extern __shared__ float sm[];
    float* AsB = sm;
    float* BsB = sm + NSTG * STG_F;

    const int tid = threadIdx.x;
    const int bm = blockIdx.y * 128;
    const int lane = tid & 31;
    const int w = tid >> 5;
    const int wm = w >> 2;
    const int wn = w & 3;

    float acc[4][4][4];
    #pragma unroll
    for (int i = 0; i < 4; i++)
        #pragma unroll
        for (int j = 0; j < 4; j++)
            #pragma unroll
            for (int r = 0; r < 4; r++) acc[i][j][r] = 0.0f;

    const float* Ag = A + (size_t)bm * KD;
    const float* Bg = Bt;

    auto prefetch = [&](int ch, int st) {
        float* as = AsB + st * STG_F;
        float* bs = BsB + st * STG_F;
        #pragma unroll
        for (int it = 0; it < 4; it++) {
            int idx = tid + it * 256;
            int r = idx >> 3, c4 = idx & 7;
            cp16(as + r * SPAD + c4 * 4, Ag + (size_t)r * KD + ch * KC + c4 * 4);
            cp16(bs + r * SPAD + c4 * 4, Bg + (size_t)r * KD + ch * KC + c4 * 4);
        }
    };

    auto compute = [&](int st) {
        const float* pa = AsB + st * STG_F
                        + (wm * 64 + (lane >> 2)) * SPAD + 2 * (lane & 3);
        const float* pb = BsB + st * STG_F
                        + (wn * 32 + (lane >> 2)) * SPAD + 2 * (lane & 3);
        uint32_t a[2][4][4], b[2][4][2];

        auto load_frag = [&](int buf, int ks) {
            const int k0 = ks * 16;
            #pragma unroll
            for (int mt = 0; mt < 4; mt++) {
                const float* p = pa + mt * 16 * SPAD + k0;
                a[buf][mt][0] = pkh2(p[0], p[1]);
                a[buf][mt][1] = pkh2(p[8 * SPAD], p[8 * SPAD + 1]);
                a[buf][mt][2] = pkh2(p[8], p[9]);
                a[buf][mt][3] = pkh2(p[8 * SPAD + 8], p[8 * SPAD + 9]);
            }
            #pragma unroll
            for (int nt = 0; nt < 4; nt++) {
                const float* p = pb + nt * 8 * SPAD + k0;
                b[buf][nt][0] = pkh2(p[0], p[1]);
                b[buf][nt][1] = pkh2(p[8], p[9]);
            }
        };

        load_frag(0, 0);
        #pragma unroll
        for (int ks = 0; ks < KC / 16; ks++) {      // 2 k16 steps
            const int cur = ks & 1;
            if (ks + 1 < KC / 16) load_frag(cur ^ 1, ks + 1);
            #pragma unroll
            for (int mt = 0; mt < 4; mt++)
                #pragma unroll
                for (int nt = 0; nt < 4; nt++)
                    MMA_F16(acc[mt][nt], a[cur][mt], b[cur][nt]);
        }
    };

    prefetch(0, 0); CP_COMMIT();
    prefetch(1, 1); CP_COMMIT();
    for (int ch = 0; ch < NCH; ch++) {
        CP_WAIT1();
        __syncthreads();
        compute(ch & 1);
        __syncthreads();
        if (ch + 2 < NCH) prefetch(ch + 2, ch & 1);
        CP_COMMIT();
    }

    // ---- transposed epilogue: row m=(b,s), col k -> beta_t[b][k][s] ----
    #pragma unroll
    for (int nt = 0; nt < 4; nt++) {
        const int col = wn * 32 + nt * 8 + 2 * (lane & 3);
        #pragma unroll
        for (int mt = 0; mt < 4; mt++) {
            const int m0 = bm + wm * 64 + mt * 16 + (lane >> 2);
            float* d0 = g_beta + ((size_t)((m0 >> 12) * KK + col)) * SS + (m0 & (SS - 1));
            d0[0]  = acc[mt][nt][0];
            d0[SS] = acc[mt][nt][1];
            const int m1 = m0 + 8;
            float* d1 = g_beta + ((size_t)((m1 >> 12) * KK + col)) * SS + (m1 & (SS - 1));
            d1[0]  = acc[mt][nt][2];
            d1[SS] = acc[mt][nt][3];
        }
    }
}

// ============================================================================
// GEMM2 (fp16 m16n8k16): y_h = fp16( sr_seq @ W_out^T + b_out ), fp32 accum.
// ============================================================================
#define SPAD_U 36
#define HSTG_U (128 * SPAD_U)

__global__ __launch_bounds__(256, 2)
void gemm_h(const __half* __restrict__ A, const __half* __restrict__ Bt,
            __half* __restrict__ C, const float* __restrict__ bias, int ldc)
{
    constexpr int KD = 128;
    constexpr int KCH = 64;
    constexpr int NCH = KD / KCH;
    extern __shared__ uint32_t smu[];
    uint32_t* AsB = smu;
    uint32_t* BsB = smu + NSTG * HSTG_U;

    const int tid = threadIdx.x;
    const int bn = blockIdx.x * 128;
    const int bm = blockIdx.y * 128;
    const int lane = tid & 31;
    const int w = tid >> 5;
    const int wm = w >> 2;
    const int wn = w & 3;

    float acc[4][4][4];
    #pragma unroll
    for (int i = 0; i < 4; i++)
        #pragma unroll
        for (int j = 0; j < 4; j++)
            #pragma unroll
            for (int r = 0; r < 4; r++) acc[i][j][r] = 0.0f;

    const __half* Ag = A + (size_t)bm * KD;
    const __half* Bg = Bt + (size_t)bn * KD;

    auto prefetch = [&](int ch, int st) {
        uint32_t* as = AsB + st * HSTG_U;
        uint32_t* bs = BsB + st * HSTG_U;
        #pragma unroll
        for (int it = 0; it < 4; it++) {
            int idx = tid + it * 256;
            int r = idx >> 3, c4 = idx & 7;
            cp16(as + r * SPAD_U + c4 * 4, Ag + (size_t)r * KD + ch * KCH + c4 * 8);
            cp16(bs + r * SPAD_U + c4 * 4, Bg + (size_t)r * KD + ch * KCH + c4 * 8);
        }
    };

    auto compute = [&](int st) {
        const uint32_t* as = AsB + st * HSTG_U
                           + (wm * 64 + (lane >> 2)) * SPAD_U + (lane & 3);
        const uint32_t* bs = BsB + st * HSTG_U
                           + (wn * 32 + (lane >> 2)) * SPAD_U + (lane & 3);
        uint32_t a[2][4][4], b[2][4][2];
        auto load_frag = [&](int buf, int ks) {
            const int k = ks * 8;
            #pragma unroll
            for (int mt = 0; mt < 4; mt++) {
                const uint32_t* p = as + mt * 16 * SPAD_U + k;
                a[buf][mt][0] = p[0];
                a[buf][mt][1] = p[8 * SPAD_U];
                a[buf][mt][2] = p[4];
                a[buf][mt][3] = p[8 * SPAD_U + 4];
            }
            #pragma unroll
            for (int nt = 0; nt < 4; nt++) {
                const uint32_t* p = bs + nt * 8 * SPAD_U + k;
                b[buf][nt][0] = p[0];
                b[buf][nt][1] = p[4];
            }
        };
        load_frag(0, 0);
        #pragma unroll
        for (int ks = 0; ks < KCH / 16; ks++) {
            const int cur = ks & 1;
            if (ks + 1 < KCH / 16) load_frag(cur ^ 1, ks + 1);
            #pragma unroll
            for (int mt = 0; mt < 4; mt++)
                #pragma unroll
                for (int nt = 0; nt < 4; nt++)
                    MMA_F16(acc[mt][nt], a[cur][mt], b[cur][nt]);
        }
    };

    prefetch(0, 0); CP_COMMIT();
    prefetch(1, 1); CP_COMMIT();
    for (int ch = 0; ch < NCH; ch++) {
        CP_WAIT1();
        __syncthreads();
        compute(ch & 1);
        __syncthreads();
        CP_COMMIT();
    }

    // ---- epilogue: fp16 y ----
    #pragma unroll
    for (int nt = 0; nt < 4; nt++) {
        const int col = bn + wn * 32 + nt * 8 + 2 * (lane & 3);
        const float2 bv = *(const float2*)(bias + col);
        #pragma unroll
        for (int mt = 0; mt < 4; mt++) {
            const int row = bm + wm * 64 + mt * 16 + (lane >> 2);
            __half2 h0 = __floats2half2_rn(acc[mt][nt][0] + bv.x, acc[mt][nt][1] + bv.y);
            __half2 h1 = __floats2half2_rn(acc[mt][nt][2] + bv.x, acc[mt][nt][3] + bv.y);
            *(__half2*)(C + (size_t)row * ldc + col) = h0;
            *(__half2*)(C + (size_t)(row + 8) * ldc + col) = h1;
        }
    }
}

// ============================================================================
// pre-convert: W_out -> fp16
// ============================================================================
__global__ __launch_bounds__(256)
void f32_to_f16(const float* __restrict__ src, __half* __restrict__ dst, int n)
{
    int i = blockIdx.x * blockDim.x + threadIdx.x;
    if (i < n) dst[i] = __float2half(src[i]);
}

// ============================================================================
// Scan over beta_t (B,K,S). CH=16 (2048 blocks) + 32-step warmup
// (decay <= 0.5 guard: truncation error <= 0.5^32). Contiguous float4 loads.
// Stores staged through smem -> coalesced 256B-row uint4 global writes
// (kills the 16x sector amplification of strided 2B stores).
// ============================================================================
#define SCAN_CH   16
#define SCAN_NCH  (SS / SCAN_CH)
#define SCAN_WARM 32

__device__ __forceinline__ bool r_is_diag(const float* R, int k) {
    bool ok = true;
    for (int i = k; i < KK * KK; i += KK) {
        int r = i / KK, c = i - r * KK;
        if (r != c && R[i] != 0.0f) ok = false;
    }
    return ok;
}

__global__ __launch_bounds__(KK)
void scan_par(const float* __restrict__ alpha, const float* __restrict__ omega,
              const float* __restrict__ R,
              float* __restrict__ srf, float* __restrict__ sif)
{
    __shared__ __half sh[SCAN_CH * KK];          // 4 KB
    const int chunk = blockIdx.x, b = blockIdx.y, k = threadIdx.x;

    const bool diag = (__syncthreads_and(r_is_diag(R, k) ? 1 : 0) != 0);
    const float mag = 1.0f / (1.0f + expf(-alpha[k]));
    const float dk = R[k * KK + k];
    const bool dec_ok = (__syncthreads_and((mag * fabsf(dk)) <= 0.5f ? 1 : 0) != 0);
    if (!(diag && dec_ok)) return;

    const float cth = cosf(omega[k]);
    const float sth = sinf(omega[k]);
    const float Ac = dk * mag * cth;
    const float Bc = dk * mag * sth;

    const int t0 = chunk * SCAN_CH;
    const int warm = (t0 >= SCAN_WARM) ? SCAN_WARM : t0;
    const float* bt = g_beta + ((size_t)(b * KK + k)) * SS + (t0 - warm);

    float sr = 0.0f, si = 0.0f;
    auto step = [&](float v) {
        float gb = dk * v;
        float nr = fmaf(Ac, sr, fmaf(-Bc, si, gb));
        float ni = fmaf(Bc, sr, Ac * si);
        sr = nr; si = ni;
    };

    const float4* p4 = (const float4*)bt;
    for (int h = 0; h < warm / 16; h++) {
        float4 wv[4];
        #pragma unroll
        for (int i = 0; i < 4; i++) wv[i] = __ldg(p4 + i);
        p4 += 4;
        #pragma unroll
        for (int i = 0; i < 4; i++) {
            step(wv[i].x); step(wv[i].y); step(wv[i].z); step(wv[i].w);
        }
    }

    // main: 16 steps -> smem rows
    float4 mv[4];
    #pragma unroll
    for (int i = 0; i < 4; i++) mv[i] = __ldg(p4 + i);
    #pragma unroll
    for (int g = 0; g < 4; g++) {
        step(mv[g].x); sh[(g * 4 + 0) * KK + k] = __float2half(sr);
        step(mv[g].y); sh[(g * 4 + 1) * KK + k] = __float2half(sr);
        step(mv[g].z); sh[(g * 4 + 2) * KK + k] = __float2half(sr);
        step(mv[g].w); sh[(g * 4 + 3) * KK + k] = __float2half(sr);
    }
    __syncthreads();

    // coalesced copy-out: 16 rows x 256 B; 256 uint4, 2 per thread
    __half* sp = g_srseq_h + ((size_t)t0 * BB + b) * KK;
    const uint4* s4 = (const uint4*)sh;
    #pragma unroll
    for (int it = 0; it < 2; it++) {
        int i = k + it * KK;              // 0..255
        int t = i >> 4, c = i & 15;
        *(uint4*)(sp + (size_t)t * (BB * KK) + c * 8) = s4[i];
    }

    if (chunk == SCAN_NCH - 1) { srf[b * KK + k] = sr; sif[b * KK + k] = si; }
}

__global__ __launch_bounds__(KK)
void scan_serial(const float* __restrict__ alpha, const float* __restrict__ omega,
                 const float* __restrict__ R,
                 float* __restrict__ srf, float* __restrict__ sif)
{
    const int b = blockIdx.x, k = threadIdx.x;

    const bool diag = (__syncthreads_and(r_is_diag(R, k) ? 1 : 0) != 0);
    const float mag = 1.0f / (1.0f + expf(-alpha[k]));
    const float dk = R[k * KK + k];
    const bool dec_ok = (__syncthreads_and((mag * fabsf(dk)) <= 0.5f ? 1 : 0) != 0);
    if (diag && dec_ok) return;   // parallel kernel handled it

    const float cth = cosf(omega[k]);
    const float sth = sinf(omega[k]);

    const float* bt = g_beta + ((size_t)(b * KK + k)) * SS;
    __half* sp = g_srseq_h + (size_t)b * KK + k;
    float sr = 0.0f, si = 0.0f;

    if (diag) {
        const float Ac = dk * mag * cth;
        const float Bc = dk * mag * sth;
        #pragma unroll 4
        for (int t = 0; t < SS; t++) {
            float gb = dk * __ldg(bt + t);
            float nr = fmaf(Ac, sr, fmaf(-Bc, si, gb));
            float ni = fmaf(Bc, sr, Ac * si);
            sr = nr; si = ni;
            sp[(size_t)t * (BB * KK)] = __float2half(sr);
        }
    } else {
        __shared__ float nrs[KK], nis[KK];
        for (int t = 0; t < SS; t++) {
            float btv = __ldg(bt + t);
            float nr = fmaf(mag * cth, sr, fmaf(-mag * sth, si, btv));
            float ni = mag * fmaf(sr, sth, si * cth);
            nrs[k] = nr; nis[k] = ni;
            __syncthreads();
            float a0 = 0.0f, a1 = 0.0f;
            #pragma unroll 8
            for (int j = 0; j < KK; j++) {
                float rj = R[j * KK + k];
                a0 = fmaf(nrs[j], rj, a0);
                a1 = fmaf(nis[j], rj, a1);
            }
            __syncthreads();
            sr = a0; si = a1;
            sp[(size_t)t * (BB * KK)] = __float2half(sr);
        }
    }
    srf[b * KK + k] = sr;
    sif[b * KK + k] = si;
}

// ============================================================================
// LayerNorm + transpose over fp16 y: row r = s*B + b -> out[b][s][:] (fp32)
// ============================================================================
__global__ __launch_bounds__(256)
void ln_kernel(const float* __restrict__ g, const float* __restrict__ bb,
               float* __restrict__ out)
{
    const int r = blockIdx.x * 8 + (threadIdx.x >> 5);
    const int lane = threadIdx.x & 31;

    const uint4* yp = (const uint4*)(g_y_h + (size_t)r * DD);

    float vals[32];
    float sum = 0.0f, sq = 0.0f;
    #pragma unroll
    for (int j = 0; j < 4; j++) {
        uint4 u = __ldg(yp + lane + j * 32);
        float2 f0 = __half22float2(*(__half2*)&u.x);
        float2 f1 = __half22float2(*(__half2*)&u.y);
        float2 f2 = __half22float2(*(__half2*)&u.z);
        float2 f3 = __half22float2(*(__half2*)&u.w);
        vals[j*8+0] = f0.x; vals[j*8+1] = f0.y;
        vals[j*8+2] = f1.x; vals[j*8+3] = f1.y;
        vals[j*8+4] = f2.x; vals[j*8+5] = f2.y;
        vals[j*8+6] = f3.x; vals[j*8+7] = f3.y;
        #pragma unroll
        for (int c = 0; c < 8; c++) {
            sum += vals[j*8+c];
            sq = fmaf(vals[j*8+c], vals[j*8+c], sq);
        }
    }
    #pragma unroll
    for (int o = 16; o > 0; o >>= 1) {
        sum += __shfl_xor_sync(0xffffffffu, sum, o);
        sq  += __shfl_xor_sync(0xffffffffu, sq,  o);
    }

    const float mu  = sum * (1.0f / DD);
    const float var = sq * (1.0f / DD) - mu * mu;
    const float inv = rsqrtf(var + LN_EPS);

    const int s = r >> 3;
    const int b = r & 7;
    float4* op = (float4*)(out + ((size_t)b * SS + s) * DD);

    #pragma unroll
    for (int j = 0; j < 4; j++) {
        #pragma unroll
        for (int h = 0; h < 2; h++) {
            const int fi = 2 * (lane + j * 32) + h;
            const float4 gg = __ldg((const float4*)g + fi);
            const float4 b4 = __ldg((const float4*)bb + fi);
            float4 o;
            o.x = fmaf((vals[j*8+h*4+0] - mu) * inv, gg.x, b4.x);
            o.y = fmaf((vals[j*8+h*4+1] - mu) * inv, gg.y, b4.y);
            o.z = fmaf((vals[j*8+h*4+2] - mu) * inv, gg.z, b4.z);
            o.w = fmaf((vals[j*8+h*4+3] - mu) * inv, gg.w, b4.w);
            op[fi] = o;
        }
    }
}

// ============================================================================
// launch
// ============================================================================
extern "C" void kernel_launch(void* const* d_in, const int* in_sizes, int n_in,
                              void* d_out, int out_size)
{
    const float* x     = (const float*)d_in[0];
    const float* alpha = (const float*)d_in[1];
    const float* omega = (const float*)d_in[2];
    const float* W_in  = (const float*)d_in[3];
    const float* R     = (const float*)d_in[4];
    const float* W_out = (const float*)d_in[5];
    const float* b_out = (const float*)d_in[6];
    const float* ln_g  = (const float*)d_in[7];
    const float* ln_b  = (const float*)d_in[8];

    float* out = (float*)d_out;                   // (B,S,D)
    float* srf = out + (size_t)BB * SS * DD;      // (B,K)
    float* sif = srf + (size_t)BB * KK;           // (B,K)

    __half* wouth_p; cudaGetSymbolAddress((void**)&wouth_p, g_wout_h);
    __half* srh_p;   cudaGetSymbolAddress((void**)&srh_p,   g_srseq_h);
    __half* yh_p;    cudaGetSymbolAddress((void**)&yh_p,    g_y_h);

    const int SMEM = 2 * NSTG * STG_F * (int)sizeof(float);   // 73728 B
    cudaFuncSetAttribute(gemm_beta, cudaFuncAttributeMaxDynamicSharedMemorySize, SMEM);
    cudaFuncSetAttribute(gemm_h,    cudaFuncAttributeMaxDynamicSharedMemorySize, SMEM);
    cudaFuncSetAttribute(gemm_beta, cudaFuncAttributePreferredSharedMemoryCarveout, 100);
    cudaFuncSetAttribute(gemm_h,    cudaFuncAttributePreferredSharedMemoryCarveout, 100);

    // 0) pre-convert W_out -> fp16
    f32_to_f16<<<(DD * KK + 255) / 256, 256>>>(W_out, wouth_p, DD * KK);

    // 1) beta^T = (x @ W_in^T)^T -> g_beta (B,K,S)   (fp16 MMA, in-flight cvt)
    gemm_beta<<<dim3(1, MM / 128), 256, SMEM>>>(x, W_in);

    // 2) scan (parallel fast path + exact fallback) -> g_srseq_h fp16
    scan_par<<<dim3(SCAN_NCH, BB), KK>>>(alpha, omega, R, srf, sif);
    scan_serial<<<BB, KK>>>(alpha, omega, R, srf, sif);

    // 3) y_h = fp16( sr_seq @ W_out^T + b_out )
    gemm_h<<<dim3(DD / 128, MM / 128), 256, SMEM>>>(srh_p, wouth_p, yh_p, b_out, DD);

    // 4) LayerNorm over fp16 y + transpose to (B,S,D) fp32
    ln_kernel<<<MM / 8, 256>>>(ln_g, ln_b, out);
}

// round 13
// speedup vs baseline: 1.1086x; 1.1086x over previous
#include <cuda_runtime.h>
#include <cuda_fp16.h>
#include <cstdint>

#define BB   8
#define SS   4096
#define DD   1024
#define KK   128
#define MM   (BB * SS)
#define LN_EPS 1e-5f

// ---------------- scratch (static device arrays; no allocations) ----------------
__device__ float  g_beta   [ (size_t)MM * KK ];  // beta TRANSPOSED: (B,K,S) 16 MB
__device__ __half g_srseq_h[ (size_t)MM * KK ];  // (S,B,K) fp16, 8 MB
__device__ __half g_y_h    [ (size_t)MM * DD ];  // (S*B, D) fp16, 64 MB
__device__ float  g_win_tf [ (size_t)KK * DD ];  // W_in  tf32-rounded
__device__ __half g_wout_h [ (size_t)DD * KK ];  // W_out fp16
__device__ int    g_fast;                        // fast-path guard flag

// ============================ helpers ============================
__device__ __forceinline__ uint32_t smem_u32(const void* p) {
    uint32_t a;
    asm("{ .reg .u64 t; cvta.to.shared.u64 t, %1; cvt.u32.u64 %0, t; }" : "=r"(a) : "l"(p));
    return a;
}
__device__ __forceinline__ uint32_t f2tf(float f) {
    uint32_t u;
    asm("cvt.rna.tf32.f32 %0, %1;" : "=r"(u) : "f"(f));
    return u;
}
__device__ __forceinline__ void cp16(void* dst, const void* src) {
    uint32_t d = smem_u32(dst);
    asm volatile("cp.async.cg.shared.global [%0], [%1], 16;" :: "r"(d), "l"(src));
}
#define CP_COMMIT() asm volatile("cp.async.commit_group;" ::: "memory")
#define CP_WAIT1()  asm volatile("cp.async.wait_group 1;"  ::: "memory")

#define MMA_TF32(c, a, b) \
    asm volatile("mma.sync.aligned.m16n8k8.row.col.f32.tf32.tf32.f32 " \
        "{%0,%1,%2,%3}, {%4,%5,%6,%7}, {%8,%9}, {%0,%1,%2,%3};" \
        : "+f"((c)[0]), "+f"((c)[1]), "+f"((c)[2]), "+f"((c)[3]) \
        : "r"((a)[0]), "r"((a)[1]), "r"((a)[2]), "r"((a)[3]), \
          "r"((b)[0]), "r"((b)[1]))

#define MMA_F16(c, a, b) \
    asm volatile("mma.sync.aligned.m16n8k16.row.col.f32.f16.f16.f32 " \
        "{%0,%1,%2,%3}, {%4,%5,%6,%7}, {%8,%9}, {%0,%1,%2,%3};" \
        : "+f"((c)[0]), "+f"((c)[1]), "+f"((c)[2]), "+f"((c)[3]) \
        : "r"((a)[0]), "r"((a)[1]), "r"((a)[2]), "r"((a)[3]), \
          "r"((b)[0]), "r"((b)[1]))

// ============================================================================
// GEMM1 (tf32, R11 version): beta^T = (x @ W_in^T)^T -> beta_t (B,K,S).
// ============================================================================
#define KC   32
#define SPAD 36
#define STG_F (128 * SPAD)
#define NSTG 2

__global__ __launch_bounds__(256, 2)
void gemm_beta(const float* __restrict__ A, const float* __restrict__ Bt)
{
    constexpr int KD = 1024;
    constexpr int NCH = KD / KC;
    extern __shared__ float sm[];
    float* AsB = sm;
    float* BsB = sm + NSTG * STG_F;

    const int tid = threadIdx.x;
    const int bm = blockIdx.y * 128;
    const int lane = tid & 31;
    const int w = tid >> 5;
    const int wm = w >> 2;
    const int wn = w & 3;

    float acc[4][4][4];
    #pragma unroll
    for (int i = 0; i < 4; i++)
        #pragma unroll
        for (int j = 0; j < 4; j++)
            #pragma unroll
            for (int r = 0; r < 4; r++) acc[i][j][r] = 0.0f;

    const float* Ag = A + (size_t)bm * KD;
    const float* Bg = Bt;

    auto prefetch = [&](int ch, int st) {
        float* as = AsB + st * STG_F;
        float* bs = BsB + st * STG_F;
        #pragma unroll
        for (int it = 0; it < 4; it++) {
            int idx = tid + it * 256;
            int r = idx >> 3, c4 = idx & 7;
            cp16(as + r * SPAD + c4 * 4, Ag + (size_t)r * KD + ch * KC + c4 * 4);
            cp16(bs + r * SPAD + c4 * 4, Bg + (size_t)r * KD + ch * KC + c4 * 4);
        }
    };

    auto compute = [&](int st) {
        const uint32_t* as = (const uint32_t*)(AsB + st * STG_F)
                           + (wm * 64 + (lane >> 2)) * SPAD + (lane & 3);
        const uint32_t* bs = (const uint32_t*)(BsB + st * STG_F)
                           + (wn * 32 + (lane >> 2)) * SPAD + (lane & 3);
        uint32_t a[2][4][4], b[2][4][2];
        auto load_frag = [&](int buf, int ks) {
            const int k = ks * 8;
            #pragma unroll
            for (int mt = 0; mt < 4; mt++) {
                const uint32_t* p = as + mt * 16 * SPAD + k;
                a[buf][mt][0] = p[0];
                a[buf][mt][1] = p[8 * SPAD];
                a[buf][mt][2] = p[4];
                a[buf][mt][3] = p[8 * SPAD + 4];
            }
            #pragma unroll
            for (int nt = 0; nt < 4; nt++) {
                const uint32_t* p = bs + nt * 8 * SPAD + k;
                b[buf][nt][0] = p[0];
                b[buf][nt][1] = p[4];
            }
        };
        load_frag(0, 0);
        #pragma unroll
        for (int ks = 0; ks < KC / 8; ks++) {
            const int cur = ks & 1;
            if (ks + 1 < KC / 8) load_frag(cur ^ 1, ks + 1);
            #pragma unroll
            for (int mt = 0; mt < 4; mt++)
                #pragma unroll
                for (int nt = 0; nt < 4; nt++)
                    MMA_TF32(acc[mt][nt], a[cur][mt], b[cur][nt]);
        }
    };

    prefetch(0, 0); CP_COMMIT();
    prefetch(1, 1); CP_COMMIT();
    for (int ch = 0; ch < NCH; ch++) {
        CP_WAIT1();
        __syncthreads();
        compute(ch & 1);
        __syncthreads();
        if (ch + 2 < NCH) prefetch(ch + 2, ch & 1);
        CP_COMMIT();
    }

    // ---- transposed epilogue: row m=(b,s), col k -> beta_t[b][k][s] ----
    #pragma unroll
    for (int nt = 0; nt < 4; nt++) {
        const int col = wn * 32 + nt * 8 + 2 * (lane & 3);
        #pragma unroll
        for (int mt = 0; mt < 4; mt++) {
            const int m0 = bm + wm * 64 + mt * 16 + (lane >> 2);
            float* d0 = g_beta + ((size_t)((m0 >> 12) * KK + col)) * SS + (m0 & (SS - 1));
            d0[0]  = acc[mt][nt][0];
            d0[SS] = acc[mt][nt][1];
            const int m1 = m0 + 8;
            float* d1 = g_beta + ((size_t)((m1 >> 12) * KK + col)) * SS + (m1 & (SS - 1));
            d1[0]  = acc[mt][nt][2];
            d1[SS] = acc[mt][nt][3];
        }
    }
}

// ============================================================================
// GEMM2 (fp16 m16n8k16): y_h = fp16( sr_seq @ W_out^T + b_out ), fp32 accum.
// ============================================================================
#define SPAD_U 36
#define HSTG_U (128 * SPAD_U)

__global__ __launch_bounds__(256, 2)
void gemm_h(const __half* __restrict__ A, const __half* __restrict__ Bt,
            __half* __restrict__ C, const float* __restrict__ bias, int ldc)
{
    constexpr int KD = 128;
    constexpr int KCH = 64;
    constexpr int NCH = KD / KCH;
    extern __shared__ uint32_t smu[];
    uint32_t* AsB = smu;
    uint32_t* BsB = smu + NSTG * HSTG_U;

    const int tid = threadIdx.x;
    const int bn = blockIdx.x * 128;
    const int bm = blockIdx.y * 128;
    const int lane = tid & 31;
    const int w = tid >> 5;
    const int wm = w >> 2;
    const int wn = w & 3;

    float acc[4][4][4];
    #pragma unroll
    for (int i = 0; i < 4; i++)
        #pragma unroll
        for (int j = 0; j < 4; j++)
            #pragma unroll
            for (int r = 0; r < 4; r++) acc[i][j][r] = 0.0f;

    const __half* Ag = A + (size_t)bm * KD;
    const __half* Bg = Bt + (size_t)bn * KD;

    auto prefetch = [&](int ch, int st) {
        uint32_t* as = AsB + st * HSTG_U;
        uint32_t* bs = BsB + st * HSTG_U;
        #pragma unroll
        for (int it = 0; it < 4; it++) {
            int idx = tid + it * 256;
            int r = idx >> 3, c4 = idx & 7;
            cp16(as + r * SPAD_U + c4 * 4, Ag + (size_t)r * KD + ch * KCH + c4 * 8);
            cp16(bs + r * SPAD_U + c4 * 4, Bg + (size_t)r * KD + ch * KCH + c4 * 8);
        }
    };

    auto compute = [&](int st) {
        const uint32_t* as = AsB + st * HSTG_U
                           + (wm * 64 + (lane >> 2)) * SPAD_U + (lane & 3);
        const uint32_t* bs = BsB + st * HSTG_U
                           + (wn * 32 + (lane >> 2)) * SPAD_U + (lane & 3);
        uint32_t a[2][4][4], b[2][4][2];
        auto load_frag = [&](int buf, int ks) {
            const int k = ks * 8;
            #pragma unroll
            for (int mt = 0; mt < 4; mt++) {
                const uint32_t* p = as + mt * 16 * SPAD_U + k;
                a[buf][mt][0] = p[0];
                a[buf][mt][1] = p[8 * SPAD_U];
                a[buf][mt][2] = p[4];
                a[buf][mt][3] = p[8 * SPAD_U + 4];
            }
            #pragma unroll
            for (int nt = 0; nt < 4; nt++) {
                const uint32_t* p = bs + nt * 8 * SPAD_U + k;
                b[buf][nt][0] = p[0];
                b[buf][nt][1] = p[4];
            }
        };
        load_frag(0, 0);
        #pragma unroll
        for (int ks = 0; ks < KCH / 16; ks++) {
            const int cur = ks & 1;
            if (ks + 1 < KCH / 16) load_frag(cur ^ 1, ks + 1);
            #pragma unroll
            for (int mt = 0; mt < 4; mt++)
                #pragma unroll
                for (int nt = 0; nt < 4; nt++)
                    MMA_F16(acc[mt][nt], a[cur][mt], b[cur][nt]);
        }
    };

    prefetch(0, 0); CP_COMMIT();
    prefetch(1, 1); CP_COMMIT();
    for (int ch = 0; ch < NCH; ch++) {
        CP_WAIT1();
        __syncthreads();
        compute(ch & 1);
        __syncthreads();
        CP_COMMIT();
    }

    // ---- epilogue: fp16 y ----
    #pragma unroll
    for (int nt = 0; nt < 4; nt++) {
        const int col = bn + wn * 32 + nt * 8 + 2 * (lane & 3);
        const float2 bv = *(const float2*)(bias + col);
        #pragma unroll
        for (int mt = 0; mt < 4; mt++) {
            const int row = bm + wm * 64 + mt * 16 + (lane >> 2);
            __half2 h0 = __floats2half2_rn(acc[mt][nt][0] + bv.x, acc[mt][nt][1] + bv.y);
            __half2 h1 = __floats2half2_rn(acc[mt][nt][2] + bv.x, acc[mt][nt][3] + bv.y);
            *(__half2*)(C + (size_t)row * ldc + col) = h0;
            *(__half2*)(C + (size_t)(row + 8) * ldc + col) = h1;
        }
    }
}

// ============================================================================
// pre-convert + fast-path guard (single tiny kernels)
// ============================================================================
__global__ __launch_bounds__(256)
void tf32_round(const float* __restrict__ src, float* __restrict__ dst, int n)
{
    int i = blockIdx.x * blockDim.x + threadIdx.x;
    if (i < n) dst[i] = __uint_as_float(f2tf(src[i]));
}
__global__ __launch_bounds__(256)
void f32_to_f16(const float* __restrict__ src, __half* __restrict__ dst, int n)
{
    int i = blockIdx.x * blockDim.x + threadIdx.x;
    if (i < n) dst[i] = __float2half(src[i]);
}

// one block, 256 threads: coalesced sweep of R (off-diag == 0) + decay check
__global__ __launch_bounds__(256)
void check_fast(const float* __restrict__ R, const float* __restrict__ alpha)
{
    const int tid = threadIdx.x;
    bool ok = true;
    for (int i = tid; i < KK * KK; i += 256) {
        int r = i >> 7, c = i & (KK - 1);
        if (r != c && R[i] != 0.0f) ok = false;
    }
    if (tid < KK) {
        float mag = 1.0f / (1.0f + expf(-alpha[tid]));
        if (mag * fabsf(R[tid * KK + tid]) > 0.5f) ok = false;
    }
    int all = __syncthreads_and(ok ? 1 : 0);
    if (tid == 0) g_fast = all;
}

// ============================================================================
// Scan over beta_t (B,K,S). CH=16 (2048 blocks) + 32-step warmup
// (decay <= 0.5 guarded by g_fast: truncation error <= 0.5^32).
// Contiguous float4 loads; smem-staged coalesced stores.
// ============================================================================
#define SCAN_CH   16
#define SCAN_NCH  (SS / SCAN_CH)
#define SCAN_WARM 32

__global__ __launch_bounds__(KK)
void scan_par(const float* __restrict__ alpha, const float* __restrict__ omega,
              const float* __restrict__ R,
              float* __restrict__ srf, float* __restrict__ sif)
{
    if (__ldg(&g_fast) == 0) return;
    __shared__ __half sh[SCAN_CH * KK];          // 4 KB
    const int chunk = blockIdx.x, b = blockIdx.y, k = threadIdx.x;

    const float mag = 1.0f / (1.0f + expf(-alpha[k]));
    const float dk = R[k * KK + k];
    const float cth = cosf(omega[k]);
    const float sth = sinf(omega[k]);
    const float Ac = dk * mag * cth;
    const float Bc = dk * mag * sth;

    const int t0 = chunk * SCAN_CH;
    const int warm = (t0 >= SCAN_WARM) ? SCAN_WARM : t0;
    const float* bt = g_beta + ((size_t)(b * KK + k)) * SS + (t0 - warm);

    float sr = 0.0f, si = 0.0f;
    auto step = [&](float v) {
        float gb = dk * v;
        float nr = fmaf(Ac, sr, fmaf(-Bc, si, gb));
        float ni = fmaf(Bc, sr, Ac * si);
        sr = nr; si = ni;
    };

    const float4* p4 = (const float4*)bt;
    for (int h = 0; h < warm / 16; h++) {
        float4 wv[4];
        #pragma unroll
        for (int i = 0; i < 4; i++) wv[i] = __ldg(p4 + i);
        p4 += 4;
        #pragma unroll
        for (int i = 0; i < 4; i++) {
            step(wv[i].x); step(wv[i].y); step(wv[i].z); step(wv[i].w);
        }
    }

    // main: 16 steps -> smem rows
    float4 mv[4];
    #pragma unroll
    for (int i = 0; i < 4; i++) mv[i] = __ldg(p4 + i);
    #pragma unroll
    for (int g = 0; g < 4; g++) {
        step(mv[g].x); sh[(g * 4 + 0) * KK + k] = __float2half(sr);
        step(mv[g].y); sh[(g * 4 + 1) * KK + k] = __float2half(sr);
        step(mv[g].z); sh[(g * 4 + 2) * KK + k] = __float2half(sr);
        step(mv[g].w); sh[(g * 4 + 3) * KK + k] = __float2half(sr);
    }
    __syncthreads();

    // coalesced copy-out: 16 rows x 256 B
    __half* sp = g_srseq_h + ((size_t)t0 * BB + b) * KK;
    const uint4* s4 = (const uint4*)sh;
    #pragma unroll
    for (int it = 0; it < 2; it++) {
        int i = k + it * KK;
        int t = i >> 4, c = i & 15;
        *(uint4*)(sp + (size_t)t * (BB * KK) + c * 8) = s4[i];
    }

    if (chunk == SCAN_NCH - 1) { srf[b * KK + k] = sr; sif[b * KK + k] = si; }
}

__global__ __launch_bounds__(KK)
void scan_serial(const float* __restrict__ alpha, const float* __restrict__ omega,
                 const float* __restrict__ R,
                 float* __restrict__ srf, float* __restrict__ sif)
{
    if (__ldg(&g_fast) != 0) return;   // fast path handled it
    const int b = blockIdx.x, k = threadIdx.x;

    // exact general path (R may be non-diagonal / decay > 0.5)
    bool diag = true;
    for (int i = k; i < KK * KK; i += KK) {
        int r = i / KK, c = i - r * KK;
        if (r != c && R[i] != 0.0f) diag = false;
    }
    const bool all_diag = (__syncthreads_and(diag ? 1 : 0) != 0);

    const float mag = 1.0f / (1.0f + expf(-alpha[k]));
    const float dk = R[k * KK + k];
    const float cth = cosf(omega[k]);
    const float sth = sinf(omega[k]);

    const float* bt = g_beta + ((size_t)(b * KK + k)) * SS;
    __half* sp = g_srseq_h + (size_t)b * KK + k;
    float sr = 0.0f, si = 0.0f;

    if (all_diag) {
        const float Ac = dk * mag * cth;
        const float Bc = dk * mag * sth;
        #pragma unroll 4
        for (int t = 0; t < SS; t++) {
            float gb = dk * __ldg(bt + t);
            float nr = fmaf(Ac, sr, fmaf(-Bc, si, gb));
            float ni = fmaf(Bc, sr, Ac * si);
            sr = nr; si = ni;
            sp[(size_t)t * (BB * KK)] = __float2half(sr);
        }
    } else {
        __shared__ float nrs[KK], nis[KK];
        for (int t = 0; t < SS; t++) {
            float btv = __ldg(bt + t);
            float nr = fmaf(mag * cth, sr, fmaf(-mag * sth, si, btv));
            float ni = mag * fmaf(sr, sth, si * cth);
            nrs[k] = nr; nis[k] = ni;
            __syncthreads();
            float a0 = 0.0f, a1 = 0.0f;
            #pragma unroll 8
            for (int j = 0; j < KK; j++) {
                float rj = R[j * KK + k];
                a0 = fmaf(nrs[j], rj, a0);
                a1 = fmaf(nis[j], rj, a1);
            }
            __syncthreads();
            sr = a0; si = a1;
            sp[(size_t)t * (BB * KK)] = __float2half(sr);
        }
    }
    srf[b * KK + k] = sr;
    sif[b * KK + k] = si;
}

// ============================================================================
// LayerNorm + transpose over fp16 y: row r = s*B + b -> out[b][s][:] (fp32)
// ============================================================================
__global__ __launch_bounds__(256)
void ln_kernel(const float* __restrict__ g, const float* __restrict__ bb,
               float* __restrict__ out)
{
    const int r = blockIdx.x * 8 + (threadIdx.x >> 5);
    const int lane = threadIdx.x & 31;

    const uint4* yp = (const uint4*)(g_y_h + (size_t)r * DD);

    float vals[32];
    float sum = 0.0f, sq = 0.0f;
    #pragma unroll
    for (int j = 0; j < 4; j++) {
        uint4 u = __ldg(yp + lane + j * 32);
        float2 f0 = __half22float2(*(__half2*)&u.x);
        float2 f1 = __half22float2(*(__half2*)&u.y);
        float2 f2 = __half22float2(*(__half2*)&u.z);
        float2 f3 = __half22float2(*(__half2*)&u.w);
        vals[j*8+0] = f0.x; vals[j*8+1] = f0.y;
        vals[j*8+2] = f1.x; vals[j*8+3] = f1.y;
        vals[j*8+4] = f2.x; vals[j*8+5] = f2.y;
        vals[j*8+6] = f3.x; vals[j*8+7] = f3.y;
        #pragma unroll
        for (int c = 0; c < 8; c++) {
            sum += vals[j*8+c];
            sq = fmaf(vals[j*8+c], vals[j*8+c], sq);
        }
    }
    #pragma unroll
    for (int o = 16; o > 0; o >>= 1) {
        sum += __shfl_xor_sync(0xffffffffu, sum, o);
        sq  += __shfl_xor_sync(0xffffffffu, sq,  o);
    }

    const float mu  = sum * (1.0f / DD);
    const float var = sq * (1.0f / DD) - mu * mu;
    const float inv = rsqrtf(var + LN_EPS);

    const int s = r >> 3;
    const int b = r & 7;
    float4* op = (float4*)(out + ((size_t)b * SS + s) * DD);

    #pragma unroll
    for (int j = 0; j < 4; j++) {
        #pragma unroll
        for (int h = 0; h < 2; h++) {
            const int fi = 2 * (lane + j * 32) + h;
            const float4 gg = __ldg((const float4*)g + fi);
            const float4 b4 = __ldg((const float4*)bb + fi);
            float4 o;
            o.x = fmaf((vals[j*8+h*4+0] - mu) * inv, gg.x, b4.x);
            o.y = fmaf((vals[j*8+h*4+1] - mu) * inv, gg.y, b4.y);
            o.z = fmaf((vals[j*8+h*4+2] - mu) * inv, gg.z, b4.z);
            o.w = fmaf((vals[j*8+h*4+3] - mu) * inv, gg.w, b4.w);
            op[fi] = o;
        }
    }
}

// ============================================================================
// launch
// ============================================================================
extern "C" void kernel_launch(void* const* d_in, const int* in_sizes, int n_in,
                              void* d_out, int out_size)
{
    const float* x     = (const float*)d_in[0];
    const float* alpha = (const float*)d_in[1];
    const float* omega = (const float*)d_in[2];
    const float* W_in  = (const float*)d_in[3];
    const float* R     = (const float*)d_in[4];
    const float* W_out = (const float*)d_in[5];
    const float* b_out = (const float*)d_in[6];
    const float* ln_g  = (const float*)d_in[7];
    const float* ln_b  = (const float*)d_in[8];

    float* out = (float*)d_out;                   // (B,S,D)
    float* srf = out + (size_t)BB * SS * DD;      // (B,K)
    float* sif = srf + (size_t)BB * KK;           // (B,K)

    float*  win_p;   cudaGetSymbolAddress((void**)&win_p,   g_win_tf);
    __half* wouth_p; cudaGetSymbolAddress((void**)&wouth_p, g_wout_h);
    __half* srh_p;   cudaGetSymbolAddress((void**)&srh_p,   g_srseq_h);
    __half* yh_p;    cudaGetSymbolAddress((void**)&yh_p,    g_y_h);

    const int SMEM = 2 * NSTG * STG_F * (int)sizeof(float);   // 73728 B
    cudaFuncSetAttribute(gemm_beta, cudaFuncAttributeMaxDynamicSharedMemorySize, SMEM);
    cudaFuncSetAttribute(gemm_h,    cudaFuncAttributeMaxDynamicSharedMemorySize, SMEM);
    cudaFuncSetAttribute(gemm_beta, cudaFuncAttributePreferredSharedMemoryCarveout, 100);
    cudaFuncSetAttribute(gemm_h,    cudaFuncAttributePreferredSharedMemoryCarveout, 100);

    // 0) pre-convert weights + fast-path guard
    tf32_round<<<(KK * DD + 255) / 256, 256>>>(W_in, win_p, KK * DD);
    f32_to_f16<<<(DD * KK + 255) / 256, 256>>>(W_out, wouth_p, DD * KK);
    check_fast<<<1, 256>>>(R, alpha);

    // 1) beta^T = (x @ W_in^T)^T -> g_beta (B,K,S)   (tf32, R11 config)
    gemm_beta<<<dim3(1, MM / 128), 256, SMEM>>>(x, win_p);

    // 2) scan (flag-guarded fast path + exact fallback)
    scan_par<<<dim3(SCAN_NCH, BB), KK>>>(alpha, omega, R, srf, sif);
    scan_serial<<<BB, KK>>>(alpha, omega, R, srf, sif);

    // 3) y_h = fp16( sr_seq @ W_out^T + b_out )
    gemm_h<<<dim3(DD / 128, MM / 128), 256, SMEM>>>(srh_p, wouth_p, yh_p, b_out, DD);

    // 4) LayerNorm over fp16 y + transpose to (B,S,D) fp32
    ln_kernel<<<MM / 8, 256>>>(ln_g, ln_b, out);
}

// round 14
// speedup vs baseline: 1.2132x; 1.0944x over previous
#include <cuda_runtime.h>
#include <cuda_fp16.h>
#include <cstdint>

#define BB   8
#define SS   4096
#define DD   1024
#define KK   128
#define MM   (BB * SS)
#define LN_EPS 1e-5f

// ---------------- scratch (static device arrays; no allocations) ----------------
__device__ float  g_beta   [ (size_t)MM * KK ];  // beta TRANSPOSED: (B,K,S) 16 MB
__device__ __half g_srseq_h[ (size_t)MM * KK ];  // (S,B,K) fp16, 8 MB
__device__ __half g_y_h    [ (size_t)MM * DD ];  // (S*B, D) fp16, 64 MB
__device__ __half g_win_h  [ (size_t)KK * DD ];  // W_in  fp16
__device__ __half g_wout_h [ (size_t)DD * KK ];  // W_out fp16
__device__ int    g_fast;                        // fast-path guard flag

// ============================ helpers ============================
__device__ __forceinline__ uint32_t smem_u32(const void* p) {
    uint32_t a;
    asm("{ .reg .u64 t; cvta.to.shared.u64 t, %1; cvt.u32.u64 %0, t; }" : "=r"(a) : "l"(p));
    return a;
}
__device__ __forceinline__ void cp16(void* dst, const void* src) {
    uint32_t d = smem_u32(dst);
    asm volatile("cp.async.cg.shared.global [%0], [%1], 16;" :: "r"(d), "l"(src));
}
__device__ __forceinline__ uint32_t pkh2(float x, float y) {
    __half2 h = __floats2half2_rn(x, y);
    return *(uint32_t*)&h;
}
#define CP_COMMIT() asm volatile("cp.async.commit_group;" ::: "memory")
#define CP_WAIT1()  asm volatile("cp.async.wait_group 1;"  ::: "memory")

#define MMA_F16(c, a, b) \
    asm volatile("mma.sync.aligned.m16n8k16.row.col.f32.f16.f16.f32 " \
        "{%0,%1,%2,%3}, {%4,%5,%6,%7}, {%8,%9}, {%0,%1,%2,%3};" \
        : "+f"((c)[0]), "+f"((c)[1]), "+f"((c)[2]), "+f"((c)[3]) \
        : "r"((a)[0]), "r"((a)[1]), "r"((a)[2]), "r"((a)[3]), \
          "r"((b)[0]), "r"((b)[1]))

// ============================================================================
// GEMM1 (fp16 MMA): beta^T = (x @ W_in^T)^T -> beta_t (B,K,S) fp32.
// A (x, fp32 global): register-staged LDG -> cvt fp16 -> STS, one chunk ahead.
// B (W_in fp16): cp.async double buffer.
// smem rows: 32 halves = 16 u32 + 4 pad (SPAD_B=20) -> fragment LDS hits all
// 32 banks exactly once (r*20 mod 32 = {0,20,8,28,16,4,24,12}).
// 256 thr = 8 warps, warp (wm,wn) owns 64x32; KC=32 (2 k16 steps); 40 KB smem.
// ============================================================================
#define KCB    32
#define SPAD_B 20                  // u32 per row
#define BSTG_U (128 * SPAD_B)      // u32 per tile stage (10 KB)
#define NSTG 2

__global__ __launch_bounds__(256, 2)
void gemm_beta(const float* __restrict__ A, const __half* __restrict__ Bt)
{
    constexpr int KD = 1024;
    constexpr int NCH = KD / KCB;   // 32
    extern __shared__ uint32_t smu[];
    uint32_t* AsB = smu;                    // [2][128][20]
    uint32_t* BsB = smu + NSTG * BSTG_U;    // [2][128][20]

    const int tid = threadIdx.x;
    const int bm = blockIdx.y * 128;
    const int lane = tid & 31;
    const int w = tid >> 5;
    const int wm = w >> 2;
    const int wn = w & 3;

    float acc[4][4][4];
    #pragma unroll
    for (int i = 0; i < 4; i++)
        #pragma unroll
        for (int j = 0; j < 4; j++)
            #pragma unroll
            for (int r = 0; r < 4; r++) acc[i][j][r] = 0.0f;

    const float*  Ag = A + (size_t)bm * KD;
    const __half* Bg = Bt;

    // A: 128 rows x 8 float4 = 1024 slots; 4 per thread
    const int ar = (tid * 4 + 0) >> 3;     // base row for this thread's 4 slots? no — use idx mapping below
    float4 areg[4];

    auto prefA = [&](int ch) {
        #pragma unroll
        for (int it = 0; it < 4; it++) {
            int idx = tid + it * 256;
            int r = idx >> 3, c4 = idx & 7;
            areg[it] = __ldg((const float4*)(Ag + (size_t)r * KD + ch * KCB) + c4);
        }
    };
    auto storeA = [&](int st) {
        uint32_t* as = AsB + st * BSTG_U;
        #pragma unroll
        for (int it = 0; it < 4; it++) {
            int idx = tid + it * 256;
            int r = idx >> 3, c4 = idx & 7;
            uint2 v = { pkh2(areg[it].x, areg[it].y), pkh2(areg[it].z, areg[it].w) };
            *(uint2*)(as + r * SPAD_B + c4 * 2) = v;
        }
    };
    // B: 128 rows x 4 cp16 = 512 slots; 2 per thread
    auto prefB = [&](int ch, int st) {
        uint32_t* bs = BsB + st * BSTG_U;
        #pragma unroll
        for (int it = 0; it < 2; it++) {
            int idx = tid + it * 256;
            int r = idx >> 2, c4 = idx & 3;
            cp16(bs + r * SPAD_B + c4 * 4, Bg + (size_t)r * KD + ch * KCB + c4 * 8);
        }
    };

    auto compute = [&](int st) {
        const uint32_t* as = AsB + st * BSTG_U
                           + (wm * 64 + (lane >> 2)) * SPAD_B + (lane & 3);
        const uint32_t* bs = BsB + st * BSTG_U
                           + (wn * 32 + (lane >> 2)) * SPAD_B + (lane & 3);
        uint32_t a[2][4][4], b[2][4][2];
        auto load_frag = [&](int buf, int ks) {
            const int k = ks * 8;
            #pragma unroll
            for (int mt = 0; mt < 4; mt++) {
                const uint32_t* p = as + mt * 16 * SPAD_B + k;
                a[buf][mt][0] = p[0];
                a[buf][mt][1] = p[8 * SPAD_B];
                a[buf][mt][2] = p[4];
                a[buf][mt][3] = p[8 * SPAD_B + 4];
            }
            #pragma unroll
            for (int nt = 0; nt < 4; nt++) {
                const uint32_t* p = bs + nt * 8 * SPAD_B + k;
                b[buf][nt][0] = p[0];
                b[buf][nt][1] = p[4];
            }
        };
        load_frag(0, 0);
        #pragma unroll
        for (int ks = 0; ks < KCB / 16; ks++) {     // 2 k16 steps
            const int cur = ks & 1;
            if (ks + 1 < KCB / 16) load_frag(cur ^ 1, ks + 1);
            #pragma unroll
            for (int mt = 0; mt < 4; mt++)
                #pragma unroll
                for (int nt = 0; nt < 4; nt++)
                    MMA_F16(acc[mt][nt], a[cur][mt], b[cur][nt]);
        }
    };

    // prologue: A chunk0 -> stage0; regs <- chunk1; B chunks 0,1 via cp.async
    prefA(0); storeA(0);
    prefA(1);
    prefB(0, 0); CP_COMMIT();
    prefB(1, 1); CP_COMMIT();

    for (int ch = 0; ch < NCH; ch++) {
        if (ch + 1 < NCH) storeA((ch + 1) & 1);   // stage not in use (synced last iter)
        if (ch + 2 < NCH) prefA(ch + 2);
        CP_WAIT1();                                // B chunk ch landed
        __syncthreads();
        compute(ch & 1);
        __syncthreads();
        if (ch + 2 < NCH) prefB(ch + 2, ch & 1);
        CP_COMMIT();
    }

    // ---- transposed epilogue: row m=(b,s), col k -> beta_t[b][k][s] ----
    #pragma unroll
    for (int nt = 0; nt < 4; nt++) {
        const int col = wn * 32 + nt * 8 + 2 * (lane & 3);
        #pragma unroll
        for (int mt = 0; mt < 4; mt++) {
            const int m0 = bm + wm * 64 + mt * 16 + (lane >> 2);
            float* d0 = g_beta + ((size_t)((m0 >> 12) * KK + col)) * SS + (m0 & (SS - 1));
            d0[0]  = acc[mt][nt][0];
            d0[SS] = acc[mt][nt][1];
            const int m1 = m0 + 8;
            float* d1 = g_beta + ((size_t)((m1 >> 12) * KK + col)) * SS + (m1 & (SS - 1));
            d1[0]  = acc[mt][nt][2];
            d1[SS] = acc[mt][nt][3];
        }
    }
}

// ============================================================================
// GEMM2 (fp16 m16n8k16): y_h = fp16( sr_seq @ W_out^T + b_out ), fp32 accum.
// (unchanged from R13)
// ============================================================================
#define SPAD_U 36
#define HSTG_U (128 * SPAD_U)

__global__ __launch_bounds__(256, 2)
void gemm_h(const __half* __restrict__ A, const __half* __restrict__ Bt,
            __half* __restrict__ C, const float* __restrict__ bias, int ldc)
{
    constexpr int KD = 128;
    constexpr int KCH = 64;
    constexpr int NCH = KD / KCH;
    extern __shared__ uint32_t smu[];
    uint32_t* AsB = smu;
    uint32_t* BsB = smu + NSTG * HSTG_U;

    const int tid = threadIdx.x;
    const int bn = blockIdx.x * 128;
    const int bm = blockIdx.y * 128;
    const int lane = tid & 31;
    const int w = tid >> 5;
    const int wm = w >> 2;
    const int wn = w & 3;

    float acc[4][4][4];
    #pragma unroll
    for (int i = 0; i < 4; i++)
        #pragma unroll
        for (int j = 0; j < 4; j++)
            #pragma unroll
            for (int r = 0; r < 4; r++) acc[i][j][r] = 0.0f;

    const __half* Ag = A + (size_t)bm * KD;
    const __half* Bg = Bt + (size_t)bn * KD;

    auto prefetch = [&](int ch, int st) {
        uint32_t* as = AsB + st * HSTG_U;
        uint32_t* bs = BsB + st * HSTG_U;
        #pragma unroll
        for (int it = 0; it < 4; it++) {
            int idx = tid + it * 256;
            int r = idx >> 3, c4 = idx & 7;
            cp16(as + r * SPAD_U + c4 * 4, Ag + (size_t)r * KD + ch * KCH + c4 * 8);
            cp16(bs + r * SPAD_U + c4 * 4, Bg + (size_t)r * KD + ch * KCH + c4 * 8);
        }
    };

    auto compute = [&](int st) {
        const uint32_t* as = AsB + st * HSTG_U
                           + (wm * 64 + (lane >> 2)) * SPAD_U + (lane & 3);
        const uint32_t* bs = BsB + st * HSTG_U
                           + (wn * 32 + (lane >> 2)) * SPAD_U + (lane & 3);
        uint32_t a[2][4][4], b[2][4][2];
        auto load_frag = [&](int buf, int ks) {
            const int k = ks * 8;
            #pragma unroll
            for (int mt = 0; mt < 4; mt++) {
                const uint32_t* p = as + mt * 16 * SPAD_U + k;
                a[buf][mt][0] = p[0];
                a[buf][mt][1] = p[8 * SPAD_U];
                a[buf][mt][2] = p[4];
                a[buf][mt][3] = p[8 * SPAD_U + 4];
            }
            #pragma unroll
            for (int nt = 0; nt < 4; nt++) {
                const uint32_t* p = bs + nt * 8 * SPAD_U + k;
                b[buf][nt][0] = p[0];
                b[buf][nt][1] = p[4];
            }
        };
        load_frag(0, 0);
        #pragma unroll
        for (int ks = 0; ks < KCH / 16; ks++) {
            const int cur = ks & 1;
            if (ks + 1 < KCH / 16) load_frag(cur ^ 1, ks + 1);
            #pragma unroll
            for (int mt = 0; mt < 4; mt++)
                #pragma unroll
                for (int nt = 0; nt < 4; nt++)
                    MMA_F16(acc[mt][nt], a[cur][mt], b[cur][nt]);
        }
    };

    prefetch(0, 0); CP_COMMIT();
    prefetch(1, 1); CP_COMMIT();
    for (int ch = 0; ch < NCH; ch++) {
        CP_WAIT1();
        __syncthreads();
        compute(ch & 1);
        __syncthreads();
        CP_COMMIT();
    }

    #pragma unroll
    for (int nt = 0; nt < 4; nt++) {
        const int col = bn + wn * 32 + nt * 8 + 2 * (lane & 3);
        const float2 bv = *(const float2*)(bias + col);
        #pragma unroll
        for (int mt = 0; mt < 4; mt++) {
            const int row = bm + wm * 64 + mt * 16 + (lane >> 2);
            __half2 h0 = __floats2half2_rn(acc[mt][nt][0] + bv.x, acc[mt][nt][1] + bv.y);
            __half2 h1 = __floats2half2_rn(acc[mt][nt][2] + bv.x, acc[mt][nt][3] + bv.y);
            *(__half2*)(C + (size_t)row * ldc + col) = h0;
            *(__half2*)(C + (size_t)(row + 8) * ldc + col) = h1;
        }
    }
}

// ============================================================================
// pre-convert + fast-path guard
// ============================================================================
__global__ __launch_bounds__(256)
void f32_to_f16(const float* __restrict__ src, __half* __restrict__ dst, int n)
{
    int i = blockIdx.x * blockDim.x + threadIdx.x;
    if (i < n) dst[i] = __float2half(src[i]);
}

__global__ __launch_bounds__(256)
void check_fast(const float* __restrict__ R, const float* __restrict__ alpha)
{
    const int tid = threadIdx.x;
    bool ok = true;
    for (int i = tid; i < KK * KK; i += 256) {
        int r = i >> 7, c = i & (KK - 1);
        if (r != c && R[i] != 0.0f) ok = false;
    }
    if (tid < KK) {
        float mag = 1.0f / (1.0f + expf(-alpha[tid]));
        if (mag * fabsf(R[tid * KK + tid]) > 0.5f) ok = false;
    }
    int all = __syncthreads_and(ok ? 1 : 0);
    if (tid == 0) g_fast = all;
}

// ============================================================================
// Scan over beta_t (B,K,S). CH=16 + 32-step warmup (g_fast guard).
// Contiguous float4 loads; smem-staged coalesced stores. (unchanged from R13)
// ============================================================================
#define SCAN_CH   16
#define SCAN_NCH  (SS / SCAN_CH)
#define SCAN_WARM 32

__global__ __launch_bounds__(KK)
void scan_par(const float* __restrict__ alpha, const float* __restrict__ omega,
              const float* __restrict__ R,
              float* __restrict__ srf, float* __restrict__ sif)
{
    if (__ldg(&g_fast) == 0) return;
    __shared__ __half sh[SCAN_CH * KK];
    const int chunk = blockIdx.x, b = blockIdx.y, k = threadIdx.x;

    const float mag = 1.0f / (1.0f + expf(-alpha[k]));
    const float dk = R[k * KK + k];
    const float cth = cosf(omega[k]);
    const float sth = sinf(omega[k]);
    const float Ac = dk * mag * cth;
    const float Bc = dk * mag * sth;

    const int t0 = chunk * SCAN_CH;
    const int warm = (t0 >= SCAN_WARM) ? SCAN_WARM : t0;
    const float* bt = g_beta + ((size_t)(b * KK + k)) * SS + (t0 - warm);

    float sr = 0.0f, si = 0.0f;
    auto step = [&](float v) {
        float gb = dk * v;
        float nr = fmaf(Ac, sr, fmaf(-Bc, si, gb));
        float ni = fmaf(Bc, sr, Ac * si);
        sr = nr; si = ni;
    };

    const float4* p4 = (const float4*)bt;
    for (int h = 0; h < warm / 16; h++) {
        float4 wv[4];
        #pragma unroll
        for (int i = 0; i < 4; i++) wv[i] = __ldg(p4 + i);
        p4 += 4;
        #pragma unroll
        for (int i = 0; i < 4; i++) {
            step(wv[i].x); step(wv[i].y); step(wv[i].z); step(wv[i].w);
        }
    }

    float4 mv[4];
    #pragma unroll
    for (int i = 0; i < 4; i++) mv[i] = __ldg(p4 + i);
    #pragma unroll
    for (int g = 0; g < 4; g++) {
        step(mv[g].x); sh[(g * 4 + 0) * KK + k] = __float2half(sr);
        step(mv[g].y); sh[(g * 4 + 1) * KK + k] = __float2half(sr);
        step(mv[g].z); sh[(g * 4 + 2) * KK + k] = __float2half(sr);
        step(mv[g].w); sh[(g * 4 + 3) * KK + k] = __float2half(sr);
    }
    __syncthreads();

    __half* sp = g_srseq_h + ((size_t)t0 * BB + b) * KK;
    const uint4* s4 = (const uint4*)sh;
    #pragma unroll
    for (int it = 0; it < 2; it++) {
        int i = k + it * KK;
        int t = i >> 4, c = i & 15;
        *(uint4*)(sp + (size_t)t * (BB * KK) + c * 8) = s4[i];
    }

    if (chunk == SCAN_NCH - 1) { srf[b * KK + k] = sr; sif[b * KK + k] = si; }
}

__global__ __launch_bounds__(KK)
void scan_serial(const float* __restrict__ alpha, const float* __restrict__ omega,
                 const float* __restrict__ R,
                 float* __restrict__ srf, float* __restrict__ sif)
{
    if (__ldg(&g_fast) != 0) return;
    const int b = blockIdx.x, k = threadIdx.x;

    bool diag = true;
    for (int i = k; i < KK * KK; i += KK) {
        int r = i / KK, c = i - r * KK;
        if (r != c && R[i] != 0.0f) diag = false;
    }
    const bool all_diag = (__syncthreads_and(diag ? 1 : 0) != 0);

    const float mag = 1.0f / (1.0f + expf(-alpha[k]));
    const float dk = R[k * KK + k];
    const float cth = cosf(omega[k]);
    const float sth = sinf(omega[k]);

    const float* bt = g_beta + ((size_t)(b * KK + k)) * SS;
    __half* sp = g_srseq_h + (size_t)b * KK + k;
    float sr = 0.0f, si = 0.0f;

    if (all_diag) {
        const float Ac = dk * mag * cth;
        const float Bc = dk * mag * sth;
        #pragma unroll 4
        for (int t = 0; t < SS; t++) {
            float gb = dk * __ldg(bt + t);
            float nr = fmaf(Ac, sr, fmaf(-Bc, si, gb));
            float ni = fmaf(Bc, sr, Ac * si);
            sr = nr; si = ni;
            sp[(size_t)t * (BB * KK)] = __float2half(sr);
        }
    } else {
        __shared__ float nrs[KK], nis[KK];
        for (int t = 0; t < SS; t++) {
            float btv = __ldg(bt + t);
            float nr = fmaf(mag * cth, sr, fmaf(-mag * sth, si, btv));
            float ni = mag * fmaf(sr, sth, si * cth);
            nrs[k] = nr; nis[k] = ni;
            __syncthreads();
            float a0 = 0.0f, a1 = 0.0f;
            #pragma unroll 8
            for (int j = 0; j < KK; j++) {
                float rj = R[j * KK + k];
                a0 = fmaf(nrs[j], rj, a0);
                a1 = fmaf(nis[j], rj, a1);
            }
            __syncthreads();
            sr = a0; si = a1;
            sp[(size_t)t * (BB * KK)] = __float2half(sr);
        }
    }
    srf[b * KK + k] = sr;
    sif[b * KK + k] = si;
}

// ============================================================================
// LayerNorm + transpose over fp16 y (unchanged from R13)
// ============================================================================
__global__ __launch_bounds__(256)
void ln_kernel(const float* __restrict__ g, const float* __restrict__ bb,
               float* __restrict__ out)
{
    const int r = blockIdx.x * 8 + (threadIdx.x >> 5);
    const int lane = threadIdx.x & 31;

    const uint4* yp = (const uint4*)(g_y_h + (size_t)r * DD);

    float vals[32];
    float sum = 0.0f, sq = 0.0f;
    #pragma unroll
    for (int j = 0; j < 4; j++) {
        uint4 u = __ldg(yp + lane + j * 32);
        float2 f0 = __half22float2(*(__half2*)&u.x);
        float2 f1 = __half22float2(*(__half2*)&u.y);
        float2 f2 = __half22float2(*(__half2*)&u.z);
        float2 f3 = __half22float2(*(__half2*)&u.w);
        vals[j*8+0] = f0.x; vals[j*8+1] = f0.y;
        vals[j*8+2] = f1.x; vals[j*8+3] = f1.y;
        vals[j*8+4] = f2.x; vals[j*8+5] = f2.y;
        vals[j*8+6] = f3.x; vals[j*8+7] = f3.y;
        #pragma unroll
        for (int c = 0; c < 8; c++) {
            sum += vals[j*8+c];
            sq = fmaf(vals[j*8+c], vals[j*8+c], sq);
        }
    }
    #pragma unroll
    for (int o = 16; o > 0; o >>= 1) {
        sum += __shfl_xor_sync(0xffffffffu, sum, o);
        sq  += __shfl_xor_sync(0xffffffffu, sq,  o);
    }

    const float mu  = sum * (1.0f / DD);
    const float var = sq * (1.0f / DD) - mu * mu;
    const float inv = rsqrtf(var + LN_EPS);

    const int s = r >> 3;
    const int b = r & 7;
    float4* op = (float4*)(out + ((size_t)b * SS + s) * DD);

    #pragma unroll
    for (int j = 0; j < 4; j++) {
        #pragma unroll
        for (int h = 0; h < 2; h++) {
            const int fi = 2 * (lane + j * 32) + h;
            const float4 gg = __ldg((const float4*)g + fi);
            const float4 b4 = __ldg((const float4*)bb + fi);
            float4 o;
            o.x = fmaf((vals[j*8+h*4+0] - mu) * inv, gg.x, b4.x);
            o.y = fmaf((vals[j*8+h*4+1] - mu) * inv, gg.y, b4.y);
            o.z = fmaf((vals[j*8+h*4+2] - mu) * inv, gg.z, b4.z);
            o.w = fmaf((vals[j*8+h*4+3] - mu) * inv, gg.w, b4.w);
            op[fi] = o;
        }
    }
}

// ============================================================================
// launch
// ============================================================================
extern "C" void kernel_launch(void* const* d_in, const int* in_sizes, int n_in,
                              void* d_out, int out_size)
{
    const float* x     = (const float*)d_in[0];
    const float* alpha = (const float*)d_in[1];
    const float* omega = (const float*)d_in[2];
    const float* W_in  = (const float*)d_in[3];
    const float* R     = (const float*)d_in[4];
    const float* W_out = (const float*)d_in[5];
    const float* b_out = (const float*)d_in[6];
    const float* ln_g  = (const float*)d_in[7];
    const float* ln_b  = (const float*)d_in[8];

    float* out = (float*)d_out;                   // (B,S,D)
    float* srf = out + (size_t)BB * SS * DD;      // (B,K)
    float* sif = srf + (size_t)BB * KK;           // (B,K)

    __half* winh_p;  cudaGetSymbolAddress((void**)&winh_p,  g_win_h);
    __half* wouth_p; cudaGetSymbolAddress((void**)&wouth_p, g_wout_h);
    __half* srh_p;   cudaGetSymbolAddress((void**)&srh_p,   g_srseq_h);
    __half* yh_p;    cudaGetSymbolAddress((void**)&yh_p,    g_y_h);

    const int SMEM1 = 2 * NSTG * BSTG_U * (int)sizeof(uint32_t);  // 40960 B
    const int SMEM2 = 2 * NSTG * HSTG_U * (int)sizeof(uint32_t);  // 73728 B
    cudaFuncSetAttribute(gemm_beta, cudaFuncAttributeMaxDynamicSharedMemorySize, SMEM1);
    cudaFuncSetAttribute(gemm_h,    cudaFuncAttributeMaxDynamicSharedMemorySize, SMEM2);
    cudaFuncSetAttribute(gemm_beta, cudaFuncAttributePreferredSharedMemoryCarveout, 100);
    cudaFuncSetAttribute(gemm_h,    cudaFuncAttributePreferredSharedMemoryCarveout, 100);

    // 0) pre-convert weights + fast-path guard
    f32_to_f16<<<(KK * DD + 255) / 256, 256>>>(W_in,  winh_p,  KK * DD);
    f32_to_f16<<<(DD * KK + 255) / 256, 256>>>(W_out, wouth_p, DD * KK);
    check_fast<<<1, 256>>>(R, alpha);

    // 1) beta^T = (x @ W_in^T)^T -> g_beta (B,K,S)   (fp16 MMA)
    gemm_beta<<<dim3(1, MM / 128), 256, SMEM1>>>(x, winh_p);

    // 2) scan (flag-guarded fast path + exact fallback)
    scan_par<<<dim3(SCAN_NCH, BB), KK>>>(alpha, omega, R, srf, sif);
    scan_serial<<<BB, KK>>>(alpha, omega, R, srf, sif);

    // 3) y_h = fp16( sr_seq @ W_out^T + b_out )
    gemm_h<<<dim3(DD / 128, MM / 128), 256, SMEM2>>>(srh_p, wouth_p, yh_p, b_out, DD);

    // 4) LayerNorm over fp16 y + transpose to (B,S,D) fp32
    ln_kernel<<<MM / 8, 256>>>(ln_g, ln_b, out);
}

// round 15
// speedup vs baseline: 1.2642x; 1.0420x over previous
#include <cuda_runtime.h>
#include <cuda_fp16.h>
#include <cstdint>

#define BB   8
#define SS   4096
#define DD   1024
#define KK   128
#define MM   (BB * SS)
#define LN_EPS 1e-5f

// ---------------- scratch (static device arrays; no allocations) ----------------
__device__ float  g_beta   [ (size_t)MM * KK ];  // beta TRANSPOSED: (B,K,S) 16 MB
__device__ __half g_srseq_h[ (size_t)MM * KK ];  // (S,B,K) fp16, 8 MB
__device__ __half g_y_h    [ (size_t)MM * DD ];  // (S*B, D) fp16, 64 MB
__device__ __half g_win_h  [ (size_t)KK * DD ];  // W_in  fp16
__device__ __half g_wout_h [ (size_t)DD * KK ];  // W_out fp16
__device__ int    g_fast;                        // fast-path guard flag

// ============================ helpers ============================
__device__ __forceinline__ uint32_t smem_u32(const void* p) {
    uint32_t a;
    asm("{ .reg .u64 t; cvta.to.shared.u64 t, %1; cvt.u32.u64 %0, t; }" : "=r"(a) : "l"(p));
    return a;
}
__device__ __forceinline__ void cp16(void* dst, const void* src) {
    uint32_t d = smem_u32(dst);
    asm volatile("cp.async.cg.shared.global [%0], [%1], 16;" :: "r"(d), "l"(src));
}
__device__ __forceinline__ uint32_t pkh2(float x, float y) {
    __half2 h = __floats2half2_rn(x, y);
    return *(uint32_t*)&h;
}
#define CP_COMMIT() asm volatile("cp.async.commit_group;" ::: "memory")
#define CP_WAIT1()  asm volatile("cp.async.wait_group 1;"  ::: "memory")

#define MMA_F16(c, a, b) \
    asm volatile("mma.sync.aligned.m16n8k16.row.col.f32.f16.f16.f32 " \
        "{%0,%1,%2,%3}, {%4,%5,%6,%7}, {%8,%9}, {%0,%1,%2,%3};" \
        : "+f"((c)[0]), "+f"((c)[1]), "+f"((c)[2]), "+f"((c)[3]) \
        : "r"((a)[0]), "r"((a)[1]), "r"((a)[2]), "r"((a)[3]), \
          "r"((b)[0]), "r"((b)[1]))

// ============================================================================
// GEMM1 (fp16 MMA): beta^T = (x @ W_in^T)^T -> beta_t (B,K,S) fp32.
// A: register-staged LDG -> cvt fp16 -> STS, 2 stages.
// B: cp.async, 3-STAGE ring -> prefB never collides with compute,
//    so ONE barrier per chunk (was 2).
// smem rows SPAD_B=20 u32 (conflict-free fragment LDS); 50 KB -> 2 CTAs/SM.
// ============================================================================
#define KCB    32
#define SPAD_B 20                  // u32 per row
#define ASTG_U (128 * SPAD_B)      // u32 per A stage (10 KB)
#define BSTG_U (128 * SPAD_B)      // u32 per B stage (10 KB)
#define NSTG 2

__global__ __launch_bounds__(256, 2)
void gemm_beta(const float* __restrict__ A, const __half* __restrict__ Bt)
{
    constexpr int KD = 1024;
    constexpr int NCH = KD / KCB;   // 32
    extern __shared__ uint32_t smu[];
    uint32_t* AsB = smu;                    // [2][128][20]
    uint32_t* BsB = smu + 2 * ASTG_U;       // [3][128][20]

    const int tid = threadIdx.x;
    const int bm = blockIdx.y * 128;
    const int lane = tid & 31;
    const int w = tid >> 5;
    const int wm = w >> 2;
    const int wn = w & 3;

    float acc[4][4][4];
    #pragma unroll
    for (int i = 0; i < 4; i++)
        #pragma unroll
        for (int j = 0; j < 4; j++)
            #pragma unroll
            for (int r = 0; r < 4; r++) acc[i][j][r] = 0.0f;

    const float*  Ag = A + (size_t)bm * KD;
    const __half* Bg = Bt;

    float4 areg[4];

    auto prefA = [&](int ch) {
        #pragma unroll
        for (int it = 0; it < 4; it++) {
            int idx = tid + it * 256;
            int r = idx >> 3, c4 = idx & 7;
            areg[it] = __ldg((const float4*)(Ag + (size_t)r * KD + ch * KCB) + c4);
        }
    };
    auto storeA = [&](int st) {
        uint32_t* as = AsB + st * ASTG_U;
        #pragma unroll
        for (int it = 0; it < 4; it++) {
            int idx = tid + it * 256;
            int r = idx >> 3, c4 = idx & 7;
            uint2 v = { pkh2(areg[it].x, areg[it].y), pkh2(areg[it].z, areg[it].w) };
            *(uint2*)(as + r * SPAD_B + c4 * 2) = v;
        }
    };
    auto prefB = [&](int ch, int st) {
        uint32_t* bs = BsB + st * BSTG_U;
        #pragma unroll
        for (int it = 0; it < 2; it++) {
            int idx = tid + it * 256;
            int r = idx >> 2, c4 = idx & 3;
            cp16(bs + r * SPAD_B + c4 * 4, Bg + (size_t)r * KD + ch * KCB + c4 * 8);
        }
    };

    auto compute = [&](int ast, int bst) {
        const uint32_t* as = AsB + ast * ASTG_U
                           + (wm * 64 + (lane >> 2)) * SPAD_B + (lane & 3);
        const uint32_t* bs = BsB + bst * BSTG_U
                           + (wn * 32 + (lane >> 2)) * SPAD_B + (lane & 3);
        uint32_t a[2][4][4], b[2][4][2];
        auto load_frag = [&](int buf, int ks) {
            const int k = ks * 8;
            #pragma unroll
            for (int mt = 0; mt < 4; mt++) {
                const uint32_t* p = as + mt * 16 * SPAD_B + k;
                a[buf][mt][0] = p[0];
                a[buf][mt][1] = p[8 * SPAD_B];
                a[buf][mt][2] = p[4];
                a[buf][mt][3] = p[8 * SPAD_B + 4];
            }
            #pragma unroll
            for (int nt = 0; nt < 4; nt++) {
                const uint32_t* p = bs + nt * 8 * SPAD_B + k;
                b[buf][nt][0] = p[0];
                b[buf][nt][1] = p[4];
            }
        };
        load_frag(0, 0);
        #pragma unroll
        for (int ks = 0; ks < KCB / 16; ks++) {     // 2 k16 steps
            const int cur = ks & 1;
            if (ks + 1 < KCB / 16) load_frag(cur ^ 1, ks + 1);
            #pragma unroll
            for (int mt = 0; mt < 4; mt++)
                #pragma unroll
                for (int nt = 0; nt < 4; nt++)
                    MMA_F16(acc[mt][nt], a[cur][mt], b[cur][nt]);
        }
    };

    // prologue: A0 -> stage0; A1 -> regs; B0,B1 committed
    prefA(0); storeA(0);
    prefA(1);
    prefB(0, 0); CP_COMMIT();
    prefB(1, 1); CP_COMMIT();

    for (int ch = 0; ch < NCH; ch++) {
        CP_WAIT1();                 // this thread's B(ch) group landed
        __syncthreads();            // + everyone's; prior compute done
        if (ch + 1 < NCH) storeA((ch + 1) & 1);   // target stage not being read
        if (ch + 2 < NCH) prefA(ch + 2);
        compute(ch & 1, ch % 3);
        if (ch + 2 < NCH) prefB(ch + 2, (ch + 2) % 3);  // 3-stage: no collision
        CP_COMMIT();
    }

    // ---- transposed epilogue: row m=(b,s), col k -> beta_t[b][k][s] ----
    #pragma unroll
    for (int nt = 0; nt < 4; nt++) {
        const int col = wn * 32 + nt * 8 + 2 * (lane & 3);
        #pragma unroll
        for (int mt = 0; mt < 4; mt++) {
            const int m0 = bm + wm * 64 + mt * 16 + (lane >> 2);
            float* d0 = g_beta + ((size_t)((m0 >> 12) * KK + col)) * SS + (m0 & (SS - 1));
            d0[0]  = acc[mt][nt][0];
            d0[SS] = acc[mt][nt][1];
            const int m1 = m0 + 8;
            float* d1 = g_beta + ((size_t)((m1 >> 12) * KK + col)) * SS + (m1 & (SS - 1));
            d1[0]  = acc[mt][nt][2];
            d1[SS] = acc[mt][nt][3];
        }
    }
}

// ============================================================================
// GEMM2 (fp16 m16n8k16): y_h = fp16( sr_seq @ W_out^T + b_out ) (unchanged)
// ============================================================================
#define SPAD_U 36
#define HSTG_U (128 * SPAD_U)

__global__ __launch_bounds__(256, 2)
void gemm_h(const __half* __restrict__ A, const __half* __restrict__ Bt,
            __half* __restrict__ C, const float* __restrict__ bias, int ldc)
{
    constexpr int KD = 128;
    constexpr int KCH = 64;
    constexpr int NCH = KD / KCH;
    extern __shared__ uint32_t smu[];
    uint32_t* AsB = smu;
    uint32_t* BsB = smu + NSTG * HSTG_U;

    const int tid = threadIdx.x;
    const int bn = blockIdx.x * 128;
    const int bm = blockIdx.y * 128;
    const int lane = tid & 31;
    const int w = tid >> 5;
    const int wm = w >> 2;
    const int wn = w & 3;

    float acc[4][4][4];
    #pragma unroll
    for (int i = 0; i < 4; i++)
        #pragma unroll
        for (int j = 0; j < 4; j++)
            #pragma unroll
            for (int r = 0; r < 4; r++) acc[i][j][r] = 0.0f;

    const __half* Ag = A + (size_t)bm * KD;
    const __half* Bg = Bt + (size_t)bn * KD;

    auto prefetch = [&](int ch, int st) {
        uint32_t* as = AsB + st * HSTG_U;
        uint32_t* bs = BsB + st * HSTG_U;
        #pragma unroll
        for (int it = 0; it < 4; it++) {
            int idx = tid + it * 256;
            int r = idx >> 3, c4 = idx & 7;
            cp16(as + r * SPAD_U + c4 * 4, Ag + (size_t)r * KD + ch * KCH + c4 * 8);
            cp16(bs + r * SPAD_U + c4 * 4, Bg + (size_t)r * KD + ch * KCH + c4 * 8);
        }
    };

    auto compute = [&](int st) {
        const uint32_t* as = AsB + st * HSTG_U
                           + (wm * 64 + (lane >> 2)) * SPAD_U + (lane & 3);
        const uint32_t* bs = BsB + st * HSTG_U
                           + (wn * 32 + (lane >> 2)) * SPAD_U + (lane & 3);
        uint32_t a[2][4][4], b[2][4][2];
        auto load_frag = [&](int buf, int ks) {
            const int k = ks * 8;
            #pragma unroll
            for (int mt = 0; mt < 4; mt++) {
                const uint32_t* p = as + mt * 16 * SPAD_U + k;
                a[buf][mt][0] = p[0];
                a[buf][mt][1] = p[8 * SPAD_U];
                a[buf][mt][2] = p[4];
                a[buf][mt][3] = p[8 * SPAD_U + 4];
            }
            #pragma unroll
            for (int nt = 0; nt < 4; nt++) {
                const uint32_t* p = bs + nt * 8 * SPAD_U + k;
                b[buf][nt][0] = p[0];
                b[buf][nt][1] = p[4];
            }
        };
        load_frag(0, 0);
        #pragma unroll
        for (int ks = 0; ks < KCH / 16; ks++) {
            const int cur = ks & 1;
            if (ks + 1 < KCH / 16) load_frag(cur ^ 1, ks + 1);
            #pragma unroll
            for (int mt = 0; mt < 4; mt++)
                #pragma unroll
                for (int nt = 0; nt < 4; nt++)
                    MMA_F16(acc[mt][nt], a[cur][mt], b[cur][nt]);
        }
    };

    prefetch(0, 0); CP_COMMIT();
    prefetch(1, 1); CP_COMMIT();
    for (int ch = 0; ch < NCH; ch++) {
        CP_WAIT1();
        __syncthreads();
        compute(ch & 1);
        __syncthreads();
        CP_COMMIT();
    }

    #pragma unroll
    for (int nt = 0; nt < 4; nt++) {
        const int col = bn + wn * 32 + nt * 8 + 2 * (lane & 3);
        const float2 bv = *(const float2*)(bias + col);
        #pragma unroll
        for (int mt = 0; mt < 4; mt++) {
            const int row = bm + wm * 64 + mt * 16 + (lane >> 2);
            __half2 h0 = __floats2half2_rn(acc[mt][nt][0] + bv.x, acc[mt][nt][1] + bv.y);
            __half2 h1 = __floats2half2_rn(acc[mt][nt][2] + bv.x, acc[mt][nt][3] + bv.y);
            *(__half2*)(C + (size_t)row * ldc + col) = h0;
            *(__half2*)(C + (size_t)(row + 8) * ldc + col) = h1;
        }
    }
}

// ============================================================================
// setup: both weight converts + fast-path guard in ONE launch.
// blocks [0,512): W_in; [512,1024): W_out; block 1024: check_fast.
// ============================================================================
__global__ __launch_bounds__(256)
void setup(const float* __restrict__ W_in, const float* __restrict__ W_out,
           const float* __restrict__ R, const float* __restrict__ alpha,
           __half* __restrict__ win_h, __half* __restrict__ wout_h)
{
    const int nb = (KK * DD) / 256;   // 512
    const int bid = blockIdx.x;
    const int tid = threadIdx.x;
    if (bid < nb) {
        int i = bid * 256 + tid;
        win_h[i] = __float2half(W_in[i]);
    } else if (bid < 2 * nb) {
        int i = (bid - nb) * 256 + tid;
        wout_h[i] = __float2half(W_out[i]);
    } else {
        bool ok = true;
        for (int i = tid; i < KK * KK; i += 256) {
            int r = i >> 7, c = i & (KK - 1);
            if (r != c && R[i] != 0.0f) ok = false;
        }
        if (tid < KK) {
            float mag = 1.0f / (1.0f + expf(-alpha[tid]));
            if (mag * fabsf(R[tid * KK + tid]) > 0.5f) ok = false;
        }
        int all = __syncthreads_and(ok ? 1 : 0);
        if (tid == 0) g_fast = all;
    }
}

// ============================================================================
// Scan over beta_t (B,K,S). CH=16 + 32-step warmup (g_fast guard).
// Contiguous float4 loads; smem-staged coalesced stores. (unchanged)
// ============================================================================
#define SCAN_CH   16
#define SCAN_NCH  (SS / SCAN_CH)
#define SCAN_WARM 32

__global__ __launch_bounds__(KK)
void scan_par(const float* __restrict__ alpha, const float* __restrict__ omega,
              const float* __restrict__ R,
              float* __restrict__ srf, float* __restrict__ sif)
{
    if (__ldg(&g_fast) == 0) return;
    __shared__ __half sh[SCAN_CH * KK];
    const int chunk = blockIdx.x, b = blockIdx.y, k = threadIdx.x;

    const float mag = 1.0f / (1.0f + expf(-alpha[k]));
    const float dk = R[k * KK + k];
    const float cth = cosf(omega[k]);
    const float sth = sinf(omega[k]);
    const float Ac = dk * mag * cth;
    const float Bc = dk * mag * sth;

    const int t0 = chunk * SCAN_CH;
    const int warm = (t0 >= SCAN_WARM) ? SCAN_WARM : t0;
    const float* bt = g_beta + ((size_t)(b * KK + k)) * SS + (t0 - warm);

    float sr = 0.0f, si = 0.0f;
    auto step = [&](float v) {
        float gb = dk * v;
        float nr = fmaf(Ac, sr, fmaf(-Bc, si, gb));
        float ni = fmaf(Bc, sr, Ac * si);
        sr = nr; si = ni;
    };

    const float4* p4 = (const float4*)bt;
    for (int h = 0; h < warm / 16; h++) {
        float4 wv[4];
        #pragma unroll
        for (int i = 0; i < 4; i++) wv[i] = __ldg(p4 + i);
        p4 += 4;
        #pragma unroll
        for (int i = 0; i < 4; i++) {
            step(wv[i].x); step(wv[i].y); step(wv[i].z); step(wv[i].w);
        }
    }

    float4 mv[4];
    #pragma unroll
    for (int i = 0; i < 4; i++) mv[i] = __ldg(p4 + i);
    #pragma unroll
    for (int g = 0; g < 4; g++) {
        step(mv[g].x); sh[(g * 4 + 0) * KK + k] = __float2half(sr);
        step(mv[g].y); sh[(g * 4 + 1) * KK + k] = __float2half(sr);
        step(mv[g].z); sh[(g * 4 + 2) * KK + k] = __float2half(sr);
        step(mv[g].w); sh[(g * 4 + 3) * KK + k] = __float2half(sr);
    }
    __syncthreads();

    __half* sp = g_srseq_h + ((size_t)t0 * BB + b) * KK;
    const uint4* s4 = (const uint4*)sh;
    #pragma unroll
    for (int it = 0; it < 2; it++) {
        int i = k + it * KK;
        int t = i >> 4, c = i & 15;
        *(uint4*)(sp + (size_t)t * (BB * KK) + c * 8) = s4[i];
    }

    if (chunk == SCAN_NCH - 1) { srf[b * KK + k] = sr; sif[b * KK + k] = si; }
}

__global__ __launch_bounds__(KK)
void scan_serial(const float* __restrict__ alpha, const float* __restrict__ omega,
                 const float* __restrict__ R,
                 float* __restrict__ srf, float* __restrict__ sif)
{
    if (__ldg(&g_fast) != 0) return;
    const int b = blockIdx.x, k = threadIdx.x;

    bool diag = true;
    for (int i = k; i < KK * KK; i += KK) {
        int r = i / KK, c = i - r * KK;
        if (r != c && R[i] != 0.0f) diag = false;
    }
    const bool all_diag = (__syncthreads_and(diag ? 1 : 0) != 0);

    const float mag = 1.0f / (1.0f + expf(-alpha[k]));
    const float dk = R[k * KK + k];
    const float cth = cosf(omega[k]);
    const float sth = sinf(omega[k]);

    const float* bt = g_beta + ((size_t)(b * KK + k)) * SS;
    __half* sp = g_srseq_h + (size_t)b * KK + k;
    float sr = 0.0f, si = 0.0f;

    if (all_diag) {
        const float Ac = dk * mag * cth;
        const float Bc = dk * mag * sth;
        #pragma unroll 4
        for (int t = 0; t < SS; t++) {
            float gb = dk * __ldg(bt + t);
            float nr = fmaf(Ac, sr, fmaf(-Bc, si, gb));
            float ni = fmaf(Bc, sr, Ac * si);
            sr = nr; si = ni;
            sp[(size_t)t * (BB * KK)] = __float2half(sr);
        }
    } else {
        __shared__ float nrs[KK], nis[KK];
        for (int t = 0; t < SS; t++) {
            float btv = __ldg(bt + t);
            float nr = fmaf(mag * cth, sr, fmaf(-mag * sth, si, btv));
            float ni = mag * fmaf(sr, sth, si * cth);
            nrs[k] = nr; nis[k] = ni;
            __syncthreads();
            float a0 = 0.0f, a1 = 0.0f;
            #pragma unroll 8
            for (int j = 0; j < KK; j++) {
                float rj = R[j * KK + k];
                a0 = fmaf(nrs[j], rj, a0);
                a1 = fmaf(nis[j], rj, a1);
            }
            __syncthreads();
            sr = a0; si = a1;
            sp[(size_t)t * (BB * KK)] = __float2half(sr);
        }
    }
    srf[b * KK + k] = sr;
    sif[b * KK + k] = si;
}

// ============================================================================
// LayerNorm + transpose over fp16 y (unchanged)
// ============================================================================
__global__ __launch_bounds__(256)
void ln_kernel(const float* __restrict__ g, const float* __restrict__ bb,
               float* __restrict__ out)
{
    const int r = blockIdx.x * 8 + (threadIdx.x >> 5);
    const int lane = threadIdx.x & 31;

    const uint4* yp = (const uint4*)(g_y_h + (size_t)r * DD);

    float vals[32];
    float sum = 0.0f, sq = 0.0f;
    #pragma unroll
    for (int j = 0; j < 4; j++) {
        uint4 u = __ldg(yp + lane + j * 32);
        float2 f0 = __half22float2(*(__half2*)&u.x);
        float2 f1 = __half22float2(*(__half2*)&u.y);
        float2 f2 = __half22float2(*(__half2*)&u.z);
        float2 f3 = __half22float2(*(__half2*)&u.w);
        vals[j*8+0] = f0.x; vals[j*8+1] = f0.y;
        vals[j*8+2] = f1.x; vals[j*8+3] = f1.y;
        vals[j*8+4] = f2.x; vals[j*8+5] = f2.y;
        vals[j*8+6] = f3.x; vals[j*8+7] = f3.y;
        #pragma unroll
        for (int c = 0; c < 8; c++) {
            sum += vals[j*8+c];
            sq = fmaf(vals[j*8+c], vals[j*8+c], sq);
        }
    }
    #pragma unroll
    for (int o = 16; o > 0; o >>= 1) {
        sum += __shfl_xor_sync(0xffffffffu, sum, o);
        sq  += __shfl_xor_sync(0xffffffffu, sq,  o);
    }

    const float mu  = sum * (1.0f / DD);
    const float var = sq * (1.0f / DD) - mu * mu;
    const float inv = rsqrtf(var + LN_EPS);

    const int s = r >> 3;
    const int b = r & 7;
    float4* op = (float4*)(out + ((size_t)b * SS + s) * DD);

    #pragma unroll
    for (int j = 0; j < 4; j++) {
        #pragma unroll
        for (int h = 0; h < 2; h++) {
            const int fi = 2 * (lane + j * 32) + h;
            const float4 gg = __ldg((const float4*)g + fi);
            const float4 b4 = __ldg((const float4*)bb + fi);
            float4 o;
            o.x = fmaf((vals[j*8+h*4+0] - mu) * inv, gg.x, b4.x);
            o.y = fmaf((vals[j*8+h*4+1] - mu) * inv, gg.y, b4.y);
            o.z = fmaf((vals[j*8+h*4+2] - mu) * inv, gg.z, b4.z);
            o.w = fmaf((vals[j*8+h*4+3] - mu) * inv, gg.w, b4.w);
            op[fi] = o;
        }
    }
}

// ============================================================================
// launch
// ============================================================================
extern "C" void kernel_launch(void* const* d_in, const int* in_sizes, int n_in,
                              void* d_out, int out_size)
{
    const float* x     = (const float*)d_in[0];
    const float* alpha = (const float*)d_in[1];
    const float* omega = (const float*)d_in[2];
    const float* W_in  = (const float*)d_in[3];
    const float* R     = (const float*)d_in[4];
    const float* W_out = (const float*)d_in[5];
    const float* b_out = (const float*)d_in[6];
    const float* ln_g  = (const float*)d_in[7];
    const float* ln_b  = (const float*)d_in[8];

    float* out = (float*)d_out;                   // (B,S,D)
    float* srf = out + (size_t)BB * SS * DD;      // (B,K)
    float* sif = srf + (size_t)BB * KK;           // (B,K)

    __half* winh_p;  cudaGetSymbolAddress((void**)&winh_p,  g_win_h);
    __half* wouth_p; cudaGetSymbolAddress((void**)&wouth_p, g_wout_h);
    __half* srh_p;   cudaGetSymbolAddress((void**)&srh_p,   g_srseq_h);
    __half* yh_p;    cudaGetSymbolAddress((void**)&yh_p,    g_y_h);

    const int SMEM1 = (2 * ASTG_U + 3 * BSTG_U) * (int)sizeof(uint32_t);  // 51200 B
    const int SMEM2 = 2 * NSTG * HSTG_U * (int)sizeof(uint32_t);          // 73728 B
    cudaFuncSetAttribute(gemm_beta, cudaFuncAttributeMaxDynamicSharedMemorySize, SMEM1);
    cudaFuncSetAttribute(gemm_h,    cudaFuncAttributeMaxDynamicSharedMemorySize, SMEM2);
    cudaFuncSetAttribute(gemm_beta, cudaFuncAttributePreferredSharedMemoryCarveout, 100);
    cudaFuncSetAttribute(gemm_h,    cudaFuncAttributePreferredSharedMemoryCarveout, 100);

    // 0) fused setup: W_in/W_out -> fp16, fast-path guard
    setup<<<2 * (KK * DD) / 256 + 1, 256>>>(W_in, W_out, R, alpha, winh_p, wouth_p);

    // 1) beta^T = (x @ W_in^T)^T -> g_beta (B,K,S)   (fp16 MMA, 1 barrier/chunk)
    gemm_beta<<<dim3(1, MM / 128), 256, SMEM1>>>(x, winh_p);

    // 2) scan (flag-guarded fast path + exact fallback)
    scan_par<<<dim3(SCAN_NCH, BB), KK>>>(alpha, omega, R, srf, sif);
    scan_serial<<<BB, KK>>>(alpha, omega, R, srf, sif);

    // 3) y_h = fp16( sr_seq @ W_out^T + b_out )
    gemm_h<<<dim3(DD / 128, MM / 128), 256, SMEM2>>>(srh_p, wouth_p, yh_p, b_out, DD);

    // 4) LayerNorm over fp16 y + transpose to (B,S,D) fp32
    ln_kernel<<<MM / 8, 256>>>(ln_g, ln_b, out);
}

// round 16
// speedup vs baseline: 1.2789x; 1.0116x over previous
#include <cuda_runtime.h>
#include <cuda_fp16.h>
#include <cstdint>

#define BB   8
#define SS   4096
#define DD   1024
#define KK   128
#define MM   (BB * SS)
#define LN_EPS 1e-5f

// ---------------- scratch (static device arrays; no allocations) ----------------
__device__ __half g_beta_h [ (size_t)MM * KK ];  // beta TRANSPOSED (B,K,S) fp16, 8 MB
__device__ __half g_srseq_h[ (size_t)MM * KK ];  // (S,B,K) fp16, 8 MB
__device__ __half g_y_h    [ (size_t)MM * DD ];  // (S*B, D) fp16, 64 MB
__device__ __half g_win_h  [ (size_t)KK * DD ];  // W_in  fp16
__device__ __half g_wout_h [ (size_t)DD * KK ];  // W_out fp16
__device__ int    g_fast;                        // fast-path guard flag

// ============================ helpers ============================
__device__ __forceinline__ uint32_t smem_u32(const void* p) {
    uint32_t a;
    asm("{ .reg .u64 t; cvta.to.shared.u64 t, %1; cvt.u32.u64 %0, t; }" : "=r"(a) : "l"(p));
    return a;
}
__device__ __forceinline__ void cp16(void* dst, const void* src) {
    uint32_t d = smem_u32(dst);
    asm volatile("cp.async.cg.shared.global [%0], [%1], 16;" :: "r"(d), "l"(src));
}
__device__ __forceinline__ uint32_t pkh2(float x, float y) {
    __half2 h = __floats2half2_rn(x, y);
    return *(uint32_t*)&h;
}
#define CP_COMMIT() asm volatile("cp.async.commit_group;" ::: "memory")
#define CP_WAIT1()  asm volatile("cp.async.wait_group 1;"  ::: "memory")

#define MMA_F16(c, a, b) \
    asm volatile("mma.sync.aligned.m16n8k16.row.col.f32.f16.f16.f32 " \
        "{%0,%1,%2,%3}, {%4,%5,%6,%7}, {%8,%9}, {%0,%1,%2,%3};" \
        : "+f"((c)[0]), "+f"((c)[1]), "+f"((c)[2]), "+f"((c)[3]) \
        : "r"((a)[0]), "r"((a)[1]), "r"((a)[2]), "r"((a)[3]), \
          "r"((b)[0]), "r"((b)[1]))

// ============================================================================
// GEMM1 (fp16 MMA): beta^T = fp16( (x @ W_in^T)^T ) -> beta_t (B,K,S) fp16.
// A: register-staged LDG -> cvt fp16 -> STS, 2 stages.
// B: cp.async 3-stage ring -> ONE barrier per chunk.
// ============================================================================
#define KCB    32
#define SPAD_B 20
#define ASTG_U (128 * SPAD_B)
#define BSTG_U (128 * SPAD_B)
#define NSTG 2

__global__ __launch_bounds__(256, 2)
void gemm_beta(const float* __restrict__ A, const __half* __restrict__ Bt)
{
    constexpr int KD = 1024;
    constexpr int NCH = KD / KCB;
    extern __shared__ uint32_t smu[];
    uint32_t* AsB = smu;                    // [2][128][20]
    uint32_t* BsB = smu + 2 * ASTG_U;       // [3][128][20]

    const int tid = threadIdx.x;
    const int bm = blockIdx.y * 128;
    const int lane = tid & 31;
    const int w = tid >> 5;
    const int wm = w >> 2;
    const int wn = w & 3;

    float acc[4][4][4];
    #pragma unroll
    for (int i = 0; i < 4; i++)
        #pragma unroll
        for (int j = 0; j < 4; j++)
            #pragma unroll
            for (int r = 0; r < 4; r++) acc[i][j][r] = 0.0f;

    const float*  Ag = A + (size_t)bm * KD;
    const __half* Bg = Bt;

    float4 areg[4];

    auto prefA = [&](int ch) {
        #pragma unroll
        for (int it = 0; it < 4; it++) {
            int idx = tid + it * 256;
            int r = idx >> 3, c4 = idx & 7;
            areg[it] = __ldg((const float4*)(Ag + (size_t)r * KD + ch * KCB) + c4);
        }
    };
    auto storeA = [&](int st) {
        uint32_t* as = AsB + st * ASTG_U;
        #pragma unroll
        for (int it = 0; it < 4; it++) {
            int idx = tid + it * 256;
            int r = idx >> 3, c4 = idx & 7;
            uint2 v = { pkh2(areg[it].x, areg[it].y), pkh2(areg[it].z, areg[it].w) };
            *(uint2*)(as + r * SPAD_B + c4 * 2) = v;
        }
    };
    auto prefB = [&](int ch, int st) {
        uint32_t* bs = BsB + st * BSTG_U;
        #pragma unroll
        for (int it = 0; it < 2; it++) {
            int idx = tid + it * 256;
            int r = idx >> 2, c4 = idx & 3;
            cp16(bs + r * SPAD_B + c4 * 4, Bg + (size_t)r * KD + ch * KCB + c4 * 8);
        }
    };

    auto compute = [&](int ast, int bst) {
        const uint32_t* as = AsB + ast * ASTG_U
                           + (wm * 64 + (lane >> 2)) * SPAD_B + (lane & 3);
        const uint32_t* bs = BsB + bst * BSTG_U
                           + (wn * 32 + (lane >> 2)) * SPAD_B + (lane & 3);
        uint32_t a[2][4][4], b[2][4][2];
        auto load_frag = [&](int buf, int ks) {
            const int k = ks * 8;
            #pragma unroll
            for (int mt = 0; mt < 4; mt++) {
                const uint32_t* p = as + mt * 16 * SPAD_B + k;
                a[buf][mt][0] = p[0];
                a[buf][mt][1] = p[8 * SPAD_B];
                a[buf][mt][2] = p[4];
                a[buf][mt][3] = p[8 * SPAD_B + 4];
            }
            #pragma unroll
            for (int nt = 0; nt < 4; nt++) {
                const uint32_t* p = bs + nt * 8 * SPAD_B + k;
                b[buf][nt][0] = p[0];
                b[buf][nt][1] = p[4];
            }
        };
        load_frag(0, 0);
        #pragma unroll
        for (int ks = 0; ks < KCB / 16; ks++) {
            const int cur = ks & 1;
            if (ks + 1 < KCB / 16) load_frag(cur ^ 1, ks + 1);
            #pragma unroll
            for (int mt = 0; mt < 4; mt++)
                #pragma unroll
                for (int nt = 0; nt < 4; nt++)
                    MMA_F16(acc[mt][nt], a[cur][mt], b[cur][nt]);
        }
    };

    prefA(0); storeA(0);
    prefA(1);
    prefB(0, 0); CP_COMMIT();
    prefB(1, 1); CP_COMMIT();

    for (int ch = 0; ch < NCH; ch++) {
        CP_WAIT1();
        __syncthreads();
        if (ch + 1 < NCH) storeA((ch + 1) & 1);
        if (ch + 2 < NCH) prefA(ch + 2);
        compute(ch & 1, ch % 3);
        if (ch + 2 < NCH) prefB(ch + 2, (ch + 2) % 3);
        CP_COMMIT();
    }

    // ---- transposed epilogue (fp16): row m=(b,s), col k -> beta_t[b][k][s] ----
    #pragma unroll
    for (int nt = 0; nt < 4; nt++) {
        const int col = wn * 32 + nt * 8 + 2 * (lane & 3);
        #pragma unroll
        for (int mt = 0; mt < 4; mt++) {
            const int m0 = bm + wm * 64 + mt * 16 + (lane >> 2);
            __half* d0 = g_beta_h + ((size_t)((m0 >> 12) * KK + col)) * SS + (m0 & (SS - 1));
            d0[0]  = __float2half(acc[mt][nt][0]);
            d0[SS] = __float2half(acc[mt][nt][1]);
            const int m1 = m0 + 8;
            __half* d1 = g_beta_h + ((size_t)((m1 >> 12) * KK + col)) * SS + (m1 & (SS - 1));
            d1[0]  = __float2half(acc[mt][nt][2]);
            d1[SS] = __float2half(acc[mt][nt][3]);
        }
    }
}

// ============================================================================
// GEMM2 (fp16 m16n8k16): y_h = fp16( sr_seq @ W_out^T + b_out ) (unchanged)
// ============================================================================
#define SPAD_U 36
#define HSTG_U (128 * SPAD_U)

__global__ __launch_bounds__(256, 2)
void gemm_h(const __half* __restrict__ A, const __half* __restrict__ Bt,
            __half* __restrict__ C, const float* __restrict__ bias, int ldc)
{
    constexpr int KD = 128;
    constexpr int KCH = 64;
    constexpr int NCH = KD / KCH;
    extern __shared__ uint32_t smu[];
    uint32_t* AsB = smu;
    uint32_t* BsB = smu + NSTG * HSTG_U;

    const int tid = threadIdx.x;
    const int bn = blockIdx.x * 128;
    const int bm = blockIdx.y * 128;
    const int lane = tid & 31;
    const int w = tid >> 5;
    const int wm = w >> 2;
    const int wn = w & 3;

    float acc[4][4][4];
    #pragma unroll
    for (int i = 0; i < 4; i++)
        #pragma unroll
        for (int j = 0; j < 4; j++)
            #pragma unroll
            for (int r = 0; r < 4; r++) acc[i][j][r] = 0.0f;

    const __half* Ag = A + (size_t)bm * KD;
    const __half* Bg = Bt + (size_t)bn * KD;

    auto prefetch = [&](int ch, int st) {
        uint32_t* as = AsB + st * HSTG_U;
        uint32_t* bs = BsB + st * HSTG_U;
        #pragma unroll
        for (int it = 0; it < 4; it++) {
            int idx = tid + it * 256;
            int r = idx >> 3, c4 = idx & 7;
            cp16(as + r * SPAD_U + c4 * 4, Ag + (size_t)r * KD + ch * KCH + c4 * 8);
            cp16(bs + r * SPAD_U + c4 * 4, Bg + (size_t)r * KD + ch * KCH + c4 * 8);
        }
    };

    auto compute = [&](int st) {
        const uint32_t* as = AsB + st * HSTG_U
                           + (wm * 64 + (lane >> 2)) * SPAD_U + (lane & 3);
        const uint32_t* bs = BsB + st * HSTG_U
                           + (wn * 32 + (lane >> 2)) * SPAD_U + (lane & 3);
        uint32_t a[2][4][4], b[2][4][2];
        auto load_frag = [&](int buf, int ks) {
            const int k = ks * 8;
            #pragma unroll
            for (int mt = 0; mt < 4; mt++) {
                const uint32_t* p = as + mt * 16 * SPAD_U + k;
                a[buf][mt][0] = p[0];
                a[buf][mt][1] = p[8 * SPAD_U];
                a[buf][mt][2] = p[4];
                a[buf][mt][3] = p[8 * SPAD_U + 4];
            }
            #pragma unroll
            for (int nt = 0; nt < 4; nt++) {
                const uint32_t* p = bs + nt * 8 * SPAD_U + k;
                b[buf][nt][0] = p[0];
                b[buf][nt][1] = p[4];
            }
        };
        load_frag(0, 0);
        #pragma unroll
        for (int ks = 0; ks < KCH / 16; ks++) {
            const int cur = ks & 1;
            if (ks + 1 < KCH / 16) load_frag(cur ^ 1, ks + 1);
            #pragma unroll
            for (int mt = 0; mt < 4; mt++)
                #pragma unroll
                for (int nt = 0; nt < 4; nt++)
                    MMA_F16(acc[mt][nt], a[cur][mt], b[cur][nt]);
        }
    };

    prefetch(0, 0); CP_COMMIT();
    prefetch(1, 1); CP_COMMIT();
    for (int ch = 0; ch < NCH; ch++) {
        CP_WAIT1();
        __syncthreads();
        compute(ch & 1);
        __syncthreads();
        CP_COMMIT();
    }

    #pragma unroll
    for (int nt = 0; nt < 4; nt++) {
        const int col = bn + wn * 32 + nt * 8 + 2 * (lane & 3);
        const float2 bv = *(const float2*)(bias + col);
        #pragma unroll
        for (int mt = 0; mt < 4; mt++) {
            const int row = bm + wm * 64 + mt * 16 + (lane >> 2);
            __half2 h0 = __floats2half2_rn(acc[mt][nt][0] + bv.x, acc[mt][nt][1] + bv.y);
            __half2 h1 = __floats2half2_rn(acc[mt][nt][2] + bv.x, acc[mt][nt][3] + bv.y);
            *(__half2*)(C + (size_t)row * ldc + col) = h0;
            *(__half2*)(C + (size_t)(row + 8) * ldc + col) = h1;
        }
    }
}

// ============================================================================
// setup: weight converts + fast-path guard in ONE launch (unchanged)
// ============================================================================
__global__ __launch_bounds__(256)
void setup(const float* __restrict__ W_in, const float* __restrict__ W_out,
           const float* __restrict__ R, const float* __restrict__ alpha,
           __half* __restrict__ win_h, __half* __restrict__ wout_h)
{
    const int nb = (KK * DD) / 256;   // 512
    const int bid = blockIdx.x;
    const int tid = threadIdx.x;
    if (bid < nb) {
        int i = bid * 256 + tid;
        win_h[i] = __float2half(W_in[i]);
    } else if (bid < 2 * nb) {
        int i = (bid - nb) * 256 + tid;
        wout_h[i] = __float2half(W_out[i]);
    } else {
        bool ok = true;
        for (int i = tid; i < KK * KK; i += 256) {
            int r = i >> 7, c = i & (KK - 1);
            if (r != c && R[i] != 0.0f) ok = false;
        }
        if (tid < KK) {
            float mag = 1.0f / (1.0f + expf(-alpha[tid]));
            if (mag * fabsf(R[tid * KK + tid]) > 0.5f) ok = false;
        }
        int all = __syncthreads_and(ok ? 1 : 0);
        if (tid == 0) g_fast = all;
    }
}

// ============================================================================
// Scan over fp16 beta_t (B,K,S). CH=16 + 32-step warmup (g_fast guard).
// uint4 loads = 8 halves each; smem-staged coalesced stores.
// ============================================================================
#define SCAN_CH   16
#define SCAN_NCH  (SS / SCAN_CH)
#define SCAN_WARM 32

__device__ __forceinline__ void unpack8(uint4 u, float* f) {
    float2 a = __half22float2(*(__half2*)&u.x);
    float2 b = __half22float2(*(((__half2*)&u.x) + 1));
    float2 c = __half22float2(*(__half2*)&u.z);
    float2 d = __half22float2(*(((__half2*)&u.z) + 1));
    f[0] = a.x; f[1] = a.y; f[2] = b.x; f[3] = b.y;
    f[4] = c.x; f[5] = c.y; f[6] = d.x; f[7] = d.y;
}

__global__ __launch_bounds__(KK)
void scan_par(const float* __restrict__ alpha, const float* __restrict__ omega,
              const float* __restrict__ R,
              float* __restrict__ srf, float* __restrict__ sif)
{
    if (__ldg(&g_fast) == 0) return;
    __shared__ __half sh[SCAN_CH * KK];
    const int chunk = blockIdx.x, b = blockIdx.y, k = threadIdx.x;

    const float mag = 1.0f / (1.0f + expf(-alpha[k]));
    const float dk = R[k * KK + k];
    const float cth = cosf(omega[k]);
    const float sth = sinf(omega[k]);
    const float Ac = dk * mag * cth;
    const float Bc = dk * mag * sth;

    const int t0 = chunk * SCAN_CH;
    const int warm = (t0 >= SCAN_WARM) ? SCAN_WARM : t0;   // 0, 16, or 32
    const __half* bt = g_beta_h + ((size_t)(b * KK + k)) * SS + (t0 - warm);

    float sr = 0.0f, si = 0.0f;
    auto step = [&](float v) {
        float gb = dk * v;
        float nr = fmaf(Ac, sr, fmaf(-Bc, si, gb));
        float ni = fmaf(Bc, sr, Ac * si);
        sr = nr; si = ni;
    };

    const uint4* p4 = (const uint4*)bt;    // 8 halves per uint4; 16B aligned
    for (int h = 0; h < warm / 8; h++) {
        float f[8];
        unpack8(__ldg(p4), f);
        p4++;
        #pragma unroll
        for (int i = 0; i < 8; i++) step(f[i]);
    }

    // main: 16 steps = 2 uint4
    uint4 m0 = __ldg(p4), m1 = __ldg(p4 + 1);
    float f0[8], f1[8];
    unpack8(m0, f0); unpack8(m1, f1);

    #pragma unroll
    for (int i = 0; i < 8; i++) {
        step(f0[i]); sh[i * KK + k] = __float2half(sr);
    }
    #pragma unroll
    for (int i = 0; i < 8; i++) {
        step(f1[i]); sh[(8 + i) * KK + k] = __float2half(sr);
    }
    __syncthreads();

    __half* sp = g_srseq_h + ((size_t)t0 * BB + b) * KK;
    const uint4* s4 = (const uint4*)sh;
    #pragma unroll
    for (int it = 0; it < 2; it++) {
        int i = k + it * KK;
        int t = i >> 4, c = i & 15;
        *(uint4*)(sp + (size_t)t * (BB * KK) + c * 8) = s4[i];
    }

    if (chunk == SCAN_NCH - 1) { srf[b * KK + k] = sr; sif[b * KK + k] = si; }
}

__global__ __launch_bounds__(KK)
void scan_serial(const float* __restrict__ alpha, const float* __restrict__ omega,
                 const float* __restrict__ R,
                 float* __restrict__ srf, float* __restrict__ sif)
{
    if (__ldg(&g_fast) != 0) return;
    const int b = blockIdx.x, k = threadIdx.x;

    bool diag = true;
    for (int i = k; i < KK * KK; i += KK) {
        int r = i / KK, c = i - r * KK;
        if (r != c && R[i] != 0.0f) diag = false;
    }
    const bool all_diag = (__syncthreads_and(diag ? 1 : 0) != 0);

    const float mag = 1.0f / (1.0f + expf(-alpha[k]));
    const float dk = R[k * KK + k];
    const float cth = cosf(omega[k]);
    const float sth = sinf(omega[k]);

    const __half* bt = g_beta_h + ((size_t)(b * KK + k)) * SS;
    __half* sp = g_srseq_h + (size_t)b * KK + k;
    float sr = 0.0f, si = 0.0f;

    if (all_diag) {
        const float Ac = dk * mag * cth;
        const float Bc = dk * mag * sth;
        #pragma unroll 4
        for (int t = 0; t < SS; t++) {
            float gb = dk * __half2float(__ldg(bt + t));
            float nr = fmaf(Ac, sr, fmaf(-Bc, si, gb));
            float ni = fmaf(Bc, sr, Ac * si);
            sr = nr; si = ni;
            sp[(size_t)t * (BB * KK)] = __float2half(sr);
        }
    } else {
        __shared__ float nrs[KK], nis[KK];
        for (int t = 0; t < SS; t++) {
            float btv = __half2float(__ldg(bt + t));
            float nr = fmaf(mag * cth, sr, fmaf(-mag * sth, si, btv));
            float ni = mag * fmaf(sr, sth, si * cth);
            nrs[k] = nr; nis[k] = ni;
            __syncthreads();
            float a0 = 0.0f, a1 = 0.0f;
            #pragma unroll 8
            for (int j = 0; j < KK; j++) {
                float rj = R[j * KK + k];
                a0 = fmaf(nrs[j], rj, a0);
                a1 = fmaf(nis[j], rj, a1);
            }
            __syncthreads();
            sr = a0; si = a1;
            sp[(size_t)t * (BB * KK)] = __float2half(sr);
        }
    }
    srf[b * KK + k] = sr;
    sif[b * KK + k] = si;
}

// ============================================================================
// LayerNorm + transpose over fp16 y (unchanged)
// ============================================================================
__global__ __launch_bounds__(256)
void ln_kernel(const float* __restrict__ g, const float* __restrict__ bb,
               float* __restrict__ out)
{
    const int r = blockIdx.x * 8 + (threadIdx.x >> 5);
    const int lane = threadIdx.x & 31;

    const uint4* yp = (const uint4*)(g_y_h + (size_t)r * DD);

    float vals[32];
    float sum = 0.0f, sq = 0.0f;
    #pragma unroll
    for (int j = 0; j < 4; j++) {
        uint4 u = __ldg(yp + lane + j * 32);
        unpack8(u, vals + j * 8);
        #pragma unroll
        for (int c = 0; c < 8; c++) {
            sum += vals[j*8+c];
            sq = fmaf(vals[j*8+c], vals[j*8+c], sq);
        }
    }
    #pragma unroll
    for (int o = 16; o > 0; o >>= 1) {
        sum += __shfl_xor_sync(0xffffffffu, sum, o);
        sq  += __shfl_xor_sync(0xffffffffu, sq,  o);
    }

    const float mu  = sum * (1.0f / DD);
    const float var = sq * (1.0f / DD) - mu * mu;
    const float inv = rsqrtf(var + LN_EPS);

    const int s = r >> 3;
    const int b = r & 7;
    float4* op = (float4*)(out + ((size_t)b * SS + s) * DD);

    #pragma unroll
    for (int j = 0; j < 4; j++) {
        #pragma unroll
        for (int h = 0; h < 2; h++) {
            const int fi = 2 * (lane + j * 32) + h;
            const float4 gg = __ldg((const float4*)g + fi);
            const float4 b4 = __ldg((const float4*)bb + fi);
            float4 o;
            o.x = fmaf((vals[j*8+h*4+0] - mu) * inv, gg.x, b4.x);
            o.y = fmaf((vals[j*8+h*4+1] - mu) * inv, gg.y, b4.y);
            o.z = fmaf((vals[j*8+h*4+2] - mu) * inv, gg.z, b4.z);
            o.w = fmaf((vals[j*8+h*4+3] - mu) * inv, gg.w, b4.w);
            op[fi] = o;
        }
    }
}

// ============================================================================
// launch
// ============================================================================
extern "C" void kernel_launch(void* const* d_in, const int* in_sizes, int n_in,
                              void* d_out, int out_size)
{
    const float* x     = (const float*)d_in[0];
    const float* alpha = (const float*)d_in[1];
    const float* omega = (const float*)d_in[2];
    const float* W_in  = (const float*)d_in[3];
    const float* R     = (const float*)d_in[4];
    const float* W_out = (const float*)d_in[5];
    const float* b_out = (const float*)d_in[6];
    const float* ln_g  = (const float*)d_in[7];
    const float* ln_b  = (const float*)d_in[8];

    float* out = (float*)d_out;                   // (B,S,D)
    float* srf = out + (size_t)BB * SS * DD;      // (B,K)
    float* sif = srf + (size_t)BB * KK;           // (B,K)

    __half* winh_p;  cudaGetSymbolAddress((void**)&winh_p,  g_win_h);
    __half* wouth_p; cudaGetSymbolAddress((void**)&wouth_p, g_wout_h);
    __half* srh_p;   cudaGetSymbolAddress((void**)&srh_p,   g_srseq_h);
    __half* yh_p;    cudaGetSymbolAddress((void**)&yh_p,    g_y_h);

    const int SMEM1 = (2 * ASTG_U + 3 * BSTG_U) * (int)sizeof(uint32_t);  // 51200 B
    const int SMEM2 = 2 * NSTG * HSTG_U * (int)sizeof(uint32_t);          // 73728 B
    cudaFuncSetAttribute(gemm_beta, cudaFuncAttributeMaxDynamicSharedMemorySize, SMEM1);
    cudaFuncSetAttribute(gemm_h,    cudaFuncAttributeMaxDynamicSharedMemorySize, SMEM2);
    cudaFuncSetAttribute(gemm_beta, cudaFuncAttributePreferredSharedMemoryCarveout, 100);
    cudaFuncSetAttribute(gemm_h,    cudaFuncAttributePreferredSharedMemoryCarveout, 100);

    // 0) fused setup: W_in/W_out -> fp16, fast-path guard
    setup<<<2 * (KK * DD) / 256 + 1, 256>>>(W_in, W_out, R, alpha, winh_p, wouth_p);

    // 1) beta^T = fp16( (x @ W_in^T)^T ) -> g_beta_h (B,K,S)
    gemm_beta<<<dim3(1, MM / 128), 256, SMEM1>>>(x, winh_p);

    // 2) scan (flag-guarded fast path + exact fallback)
    scan_par<<<dim3(SCAN_NCH, BB), KK>>>(alpha, omega, R, srf, sif);
    scan_serial<<<BB, KK>>>(alpha, omega, R, srf, sif);

    // 3) y_h = fp16( sr_seq @ W_out^T + b_out )
    gemm_h<<<dim3(DD / 128, MM / 128), 256, SMEM2>>>(srh_p, wouth_p, yh_p, b_out, DD);

    // 4) LayerNorm over fp16 y + transpose to (B,S,D) fp32
    ln_kernel<<<MM / 8, 256>>>(ln_g, ln_b, out);
}

// round 17
// speedup vs baseline: 1.2917x; 1.0101x over previous
#include <cuda_runtime.h>
#include <cuda_fp16.h>
#include <cstdint>

#define BB   8
#define SS   4096
#define DD   1024
#define KK   128
#define MM   (BB * SS)
#define LN_EPS 1e-5f

// ---------------- scratch (static device arrays; no allocations) ----------------
__device__ __half g_beta_h [ (size_t)MM * KK ];  // beta TRANSPOSED (B,K,S) fp16, 8 MB
__device__ __half g_srseq_h[ (size_t)MM * KK ];  // (S,B,K) fp16, 8 MB
__device__ __half g_win_h  [ (size_t)KK * DD ];  // W_in  fp16
__device__ __half g_wout_h [ (size_t)DD * KK ];  // W_out fp16
__device__ int    g_fast;                        // fast-path guard flag

// ============================ helpers ============================
__device__ __forceinline__ uint32_t smem_u32(const void* p) {
    uint32_t a;
    asm("{ .reg .u64 t; cvta.to.shared.u64 t, %1; cvt.u32.u64 %0, t; }" : "=r"(a) : "l"(p));
    return a;
}
__device__ __forceinline__ void cp16(void* dst, const void* src) {
    uint32_t d = smem_u32(dst);
    asm volatile("cp.async.cg.shared.global [%0], [%1], 16;" :: "r"(d), "l"(src));
}
__device__ __forceinline__ uint32_t pkh2(float x, float y) {
    __half2 h = __floats2half2_rn(x, y);
    return *(uint32_t*)&h;
}
__device__ __forceinline__ void unpack8(uint4 u, float* f) {
    float2 a = __half22float2(*(__half2*)&u.x);
    float2 b = __half22float2(*(((__half2*)&u.x) + 1));
    float2 c = __half22float2(*(__half2*)&u.z);
    float2 d = __half22float2(*(((__half2*)&u.z) + 1));
    f[0] = a.x; f[1] = a.y; f[2] = b.x; f[3] = b.y;
    f[4] = c.x; f[5] = c.y; f[6] = d.x; f[7] = d.y;
}
#define CP_COMMIT() asm volatile("cp.async.commit_group;" ::: "memory")
#define CP_WAIT1()  asm volatile("cp.async.wait_group 1;"  ::: "memory")

#define MMA_F16(c, a, b) \
    asm volatile("mma.sync.aligned.m16n8k16.row.col.f32.f16.f16.f32 " \
        "{%0,%1,%2,%3}, {%4,%5,%6,%7}, {%8,%9}, {%0,%1,%2,%3};" \
        : "+f"((c)[0]), "+f"((c)[1]), "+f"((c)[2]), "+f"((c)[3]) \
        : "r"((a)[0]), "r"((a)[1]), "r"((a)[2]), "r"((a)[3]), \
          "r"((b)[0]), "r"((b)[1]))

// ============================================================================
// GEMM1 (fp16 MMA): beta^T = fp16( (x @ W_in^T)^T ) -> beta_t (B,K,S) fp16.
// (unchanged from R16)
// ============================================================================
#define KCB    32
#define SPAD_B 20
#define ASTG_U (128 * SPAD_B)
#define BSTG_U (128 * SPAD_B)

__global__ __launch_bounds__(256, 2)
void gemm_beta(const float* __restrict__ A, const __half* __restrict__ Bt)
{
    constexpr int KD = 1024;
    constexpr int NCH = KD / KCB;
    extern __shared__ uint32_t smu[];
    uint32_t* AsB = smu;                    // [2][128][20]
    uint32_t* BsB = smu + 2 * ASTG_U;       // [3][128][20]

    const int tid = threadIdx.x;
    const int bm = blockIdx.y * 128;
    const int lane = tid & 31;
    const int w = tid >> 5;
    const int wm = w >> 2;
    const int wn = w & 3;

    float acc[4][4][4];
    #pragma unroll
    for (int i = 0; i < 4; i++)
        #pragma unroll
        for (int j = 0; j < 4; j++)
            #pragma unroll
            for (int r = 0; r < 4; r++) acc[i][j][r] = 0.0f;

    const float*  Ag = A + (size_t)bm * KD;
    const __half* Bg = Bt;

    float4 areg[4];

    auto prefA = [&](int ch) {
        #pragma unroll
        for (int it = 0; it < 4; it++) {
            int idx = tid + it * 256;
            int r = idx >> 3, c4 = idx & 7;
            areg[it] = __ldg((const float4*)(Ag + (size_t)r * KD + ch * KCB) + c4);
        }
    };
    auto storeA = [&](int st) {
        uint32_t* as = AsB + st * ASTG_U;
        #pragma unroll
        for (int it = 0; it < 4; it++) {
            int idx = tid + it * 256;
            int r = idx >> 3, c4 = idx & 7;
            uint2 v = { pkh2(areg[it].x, areg[it].y), pkh2(areg[it].z, areg[it].w) };
            *(uint2*)(as + r * SPAD_B + c4 * 2) = v;
        }
    };
    auto prefB = [&](int ch, int st) {
        uint32_t* bs = BsB + st * BSTG_U;
        #pragma unroll
        for (int it = 0; it < 2; it++) {
            int idx = tid + it * 256;
            int r = idx >> 2, c4 = idx & 3;
            cp16(bs + r * SPAD_B + c4 * 4, Bg + (size_t)r * KD + ch * KCB + c4 * 8);
        }
    };

    auto compute = [&](int ast, int bst) {
        const uint32_t* as = AsB + ast * ASTG_U
                           + (wm * 64 + (lane >> 2)) * SPAD_B + (lane & 3);
        const uint32_t* bs = BsB + bst * BSTG_U
                           + (wn * 32 + (lane >> 2)) * SPAD_B + (lane & 3);
        uint32_t a[2][4][4], b[2][4][2];
        auto load_frag = [&](int buf, int ks) {
            const int k = ks * 8;
            #pragma unroll
            for (int mt = 0; mt < 4; mt++) {
                const uint32_t* p = as + mt * 16 * SPAD_B + k;
                a[buf][mt][0] = p[0];
                a[buf][mt][1] = p[8 * SPAD_B];
                a[buf][mt][2] = p[4];
                a[buf][mt][3] = p[8 * SPAD_B + 4];
            }
            #pragma unroll
            for (int nt = 0; nt < 4; nt++) {
                const uint32_t* p = bs + nt * 8 * SPAD_B + k;
                b[buf][nt][0] = p[0];
                b[buf][nt][1] = p[4];
            }
        };
        load_frag(0, 0);
        #pragma unroll
        for (int ks = 0; ks < KCB / 16; ks++) {
            const int cur = ks & 1;
            if (ks + 1 < KCB / 16) load_frag(cur ^ 1, ks + 1);
            #pragma unroll
            for (int mt = 0; mt < 4; mt++)
                #pragma unroll
                for (int nt = 0; nt < 4; nt++)
                    MMA_F16(acc[mt][nt], a[cur][mt], b[cur][nt]);
        }
    };

    prefA(0); storeA(0);
    prefA(1);
    prefB(0, 0); CP_COMMIT();
    prefB(1, 1); CP_COMMIT();

    for (int ch = 0; ch < NCH; ch++) {
        CP_WAIT1();
        __syncthreads();
        if (ch + 1 < NCH) storeA((ch + 1) & 1);
        if (ch + 2 < NCH) prefA(ch + 2);
        compute(ch & 1, ch % 3);
        if (ch + 2 < NCH) prefB(ch + 2, (ch + 2) % 3);
        CP_COMMIT();
    }

    #pragma unroll
    for (int nt = 0; nt < 4; nt++) {
        const int col = wn * 32 + nt * 8 + 2 * (lane & 3);
        #pragma unroll
        for (int mt = 0; mt < 4; mt++) {
            const int m0 = bm + wm * 64 + mt * 16 + (lane >> 2);
            __half* d0 = g_beta_h + ((size_t)((m0 >> 12) * KK + col)) * SS + (m0 & (SS - 1));
            d0[0]  = __float2half(acc[mt][nt][0]);
            d0[SS] = __float2half(acc[mt][nt][1]);
            const int m1 = m0 + 8;
            __half* d1 = g_beta_h + ((size_t)((m1 >> 12) * KK + col)) * SS + (m1 & (SS - 1));
            d1[0]  = __float2half(acc[mt][nt][2]);
            d1[SS] = __float2half(acc[mt][nt][3]);
        }
    }
}

// ============================================================================
// FUSED GEMM2 + LayerNorm (gemm_hy):
// per CTA: rows bm..bm+63 of y = sr_seq @ W_out^T + b_out, all 1024 cols,
// accumulated in smem fp16 (row pad 8 halves); then in-kernel LN + transpose
// writes out[b][s][:] fp32 directly. Kills the 128 MB y round-trip + a launch.
// smem: A 64x68u32 (17 KB) + B 2x128x68u32 (70 KB) + Y 64x516u32 (132 KB) = 219 KB.
// ============================================================================
#define HPAD 68                    // u32 per A/B smem row (68%32=4 -> conflict-free)
#define A_U  (64 * HPAD)
#define B_U  (128 * HPAD)
#define YPADH 1032                 // halves per y smem row (516 u32)
#define Y_U  (64 * (YPADH / 2))

__global__ __launch_bounds__(256, 1)
void gemm_hy(const __half* __restrict__ A, const __half* __restrict__ Bt,
             const float* __restrict__ bias,
             const float* __restrict__ lng, const float* __restrict__ lnb,
             float* __restrict__ out)
{
    extern __shared__ uint32_t smu[];
    uint32_t* As = smu;                      // [64][68]
    uint32_t* Bs = smu + A_U;                // [2][128][68]
    __half*   Ys = (__half*)(smu + A_U + 2 * B_U);   // [64][1032]

    const int tid = threadIdx.x;
    const int bm = blockIdx.x * 64;
    const int lane = tid & 31;
    const int w = tid >> 5;
    const int wm = w >> 2;        // 0..1 -> 32-row halves
    const int wn = w & 3;         // 0..3 -> 32-col quarters of 128

    const __half* Ag = A + (size_t)bm * KK;

    // load A once: 64 rows x 16 cp16 = 1024; 4/thread
    #pragma unroll
    for (int it = 0; it < 4; it++) {
        int idx = tid + it * 256;
        int r = idx >> 4, c = idx & 15;
        cp16(As + r * HPAD + c * 4, Ag + (size_t)r * KK + c * 8);
    }
    // B tile nb: W_out[nb*128 .. +128), 128 rows x 16 cp16 = 2048; 8/thread
    auto prefB = [&](int nb, int st) {
        uint32_t* bs = Bs + st * B_U;
        const __half* Bg = Bt + (size_t)nb * 128 * KK;
        #pragma unroll
        for (int it = 0; it < 8; it++) {
            int idx = tid + it * 256;
            int r = idx >> 4, c = idx & 15;
            cp16(bs + r * HPAD + c * 4, Bg + (size_t)r * KK + c * 8);
        }
    };

    prefB(0, 0); CP_COMMIT();     // group 0 = {A, B0}
    prefB(1, 1); CP_COMMIT();     // group 1 = {B1}

    const uint32_t* as0 = As + (wm * 32 + (lane >> 2)) * HPAD + (lane & 3);

    for (int nb = 0; nb < 8; nb++) {
        CP_WAIT1();
        __syncthreads();

        float acc[2][4][4];
        #pragma unroll
        for (int i = 0; i < 2; i++)
            #pragma unroll
            for (int j = 0; j < 4; j++)
                #pragma unroll
                for (int r = 0; r < 4; r++) acc[i][j][r] = 0.0f;

        const uint32_t* bs0 = Bs + (nb & 1) * B_U
                            + (wn * 32 + (lane >> 2)) * HPAD + (lane & 3);
        uint32_t a[2][2][4], b[2][4][2];
        auto load_frag = [&](int buf, int ks) {
            const int k = ks * 8;
            #pragma unroll
            for (int mt = 0; mt < 2; mt++) {
                const uint32_t* p = as0 + mt * 16 * HPAD + k;
                a[buf][mt][0] = p[0];
                a[buf][mt][1] = p[8 * HPAD];
                a[buf][mt][2] = p[4];
                a[buf][mt][3] = p[8 * HPAD + 4];
            }
            #pragma unroll
            for (int nt = 0; nt < 4; nt++) {
                const uint32_t* p = bs0 + nt * 8 * HPAD + k;
                b[buf][nt][0] = p[0];
                b[buf][nt][1] = p[4];
            }
        };
        load_frag(0, 0);
        #pragma unroll
        for (int ks = 0; ks < 8; ks++) {        // K = 128 = 8 k16 steps
            const int cur = ks & 1;
            if (ks + 1 < 8) load_frag(cur ^ 1, ks + 1);
            #pragma unroll
            for (int mt = 0; mt < 2; mt++)
                #pragma unroll
                for (int nt = 0; nt < 4; nt++)
                    MMA_F16(acc[mt][nt], a[cur][mt], b[cur][nt]);
        }

        // epilogue into smem y (+ bias)
        #pragma unroll
        for (int nt = 0; nt < 4; nt++) {
            const int col = nb * 128 + wn * 32 + nt * 8 + 2 * (lane & 3);
            const float2 bv = *(const float2*)(bias + col);
            #pragma unroll
            for (int mt = 0; mt < 2; mt++) {
                const int row = wm * 32 + mt * 16 + (lane >> 2);
                __half2 h0 = __floats2half2_rn(acc[mt][nt][0] + bv.x, acc[mt][nt][1] + bv.y);
                __half2 h1 = __floats2half2_rn(acc[mt][nt][2] + bv.x, acc[mt][nt][3] + bv.y);
                *(__half2*)(Ys + (size_t)row * YPADH + col) = h0;
                *(__half2*)(Ys + (size_t)(row + 8) * YPADH + col) = h1;
            }
        }
        __syncthreads();            // Ys/B-stage safe before overwrite
        if (nb + 2 < 8) prefB(nb + 2, nb & 1);
        CP_COMMIT();
    }

    // ---- LayerNorm + transpose from smem: warp w -> rows w*8..w*8+7 ----
    #pragma unroll
    for (int rr = 0; rr < 8; rr++) {
        const int row = w * 8 + rr;
        const uint4* yp = (const uint4*)(Ys + (size_t)row * YPADH);

        float vals[32];
        float sum = 0.0f, sq = 0.0f;
        #pragma unroll
        for (int j = 0; j < 4; j++) {
            uint4 u = yp[lane + j * 32];
            unpack8(u, vals + j * 8);
            #pragma unroll
            for (int c = 0; c < 8; c++) {
                sum += vals[j * 8 + c];
                sq = fmaf(vals[j * 8 + c], vals[j * 8 + c], sq);
            }
        }
        #pragma unroll
        for (int o = 16; o > 0; o >>= 1) {
            sum += __shfl_xor_sync(0xffffffffu, sum, o);
            sq  += __shfl_xor_sync(0xffffffffu, sq,  o);
        }
        const float mu  = sum * (1.0f / DD);
        const float var = sq * (1.0f / DD) - mu * mu;
        const float inv = rsqrtf(var + LN_EPS);

        const int gm = bm + row;         // global row = s*B + b
        const int s = gm >> 3, b = gm & 7;
        float4* op = (float4*)(out + ((size_t)b * SS + s) * DD);

        #pragma unroll
        for (int j = 0; j < 4; j++) {
            #pragma unroll
            for (int h = 0; h < 2; h++) {
                const int fi = 2 * (lane + j * 32) + h;
                const float4 gg = __ldg((const float4*)lng + fi);
                const float4 b4 = __ldg((const float4*)lnb + fi);
                float4 o;
                o.x = fmaf((vals[j*8+h*4+0] - mu) * inv, gg.x, b4.x);
                o.y = fmaf((vals[j*8+h*4+1] - mu) * inv, gg.y, b4.y);
                o.z = fmaf((vals[j*8+h*4+2] - mu) * inv, gg.z, b4.z);
                o.w = fmaf((vals[j*8+h*4+3] - mu) * inv, gg.w, b4.w);
                op[fi] = o;
            }
        }
    }
}

// ============================================================================
// setup: weight converts + fast-path guard in ONE launch (unchanged)
// ============================================================================
__global__ __launch_bounds__(256)
void setup(const float* __restrict__ W_in, const float* __restrict__ W_out,
           const float* __restrict__ R, const float* __restrict__ alpha,
           __half* __restrict__ win_h, __half* __restrict__ wout_h)
{
    const int nb = (KK * DD) / 256;   // 512
    const int bid = blockIdx.x;
    const int tid = threadIdx.x;
    if (bid < nb) {
        int i = bid * 256 + tid;
        win_h[i] = __float2half(W_in[i]);
    } else if (bid < 2 * nb) {
        int i = (bid - nb) * 256 + tid;
        wout_h[i] = __float2half(W_out[i]);
    } else {
        bool ok = true;
        for (int i = tid; i < KK * KK; i += 256) {
            int r = i >> 7, c = i & (KK - 1);
            if (r != c && R[i] != 0.0f) ok = false;
        }
        if (tid < KK) {
            float mag = 1.0f / (1.0f + expf(-alpha[tid]));
            if (mag * fabsf(R[tid * KK + tid]) > 0.5f) ok = false;
        }
        int all = __syncthreads_and(ok ? 1 : 0);
        if (tid == 0) g_fast = all;
    }
}

// ============================================================================
// Scan over fp16 beta_t (B,K,S). CH=16 + 32-step warmup (g_fast guard).
// (unchanged from R16)
// ============================================================================
#define SCAN_CH   16
#define SCAN_NCH  (SS / SCAN_CH)
#define SCAN_WARM 32

__global__ __launch_bounds__(KK)
void scan_par(const float* __restrict__ alpha, const float* __restrict__ omega,
              const float* __restrict__ R,
              float* __restrict__ srf, float* __restrict__ sif)
{
    if (__ldg(&g_fast) == 0) return;
    __shared__ __half sh[SCAN_CH * KK];
    const int chunk = blockIdx.x, b = blockIdx.y, k = threadIdx.x;

    const float mag = 1.0f / (1.0f + expf(-alpha[k]));
    const float dk = R[k * KK + k];
    const float cth = cosf(omega[k]);
    const float sth = sinf(omega[k]);
    const float Ac = dk * mag * cth;
    const float Bc = dk * mag * sth;

    const int t0 = chunk * SCAN_CH;
    const int warm = (t0 >= SCAN_WARM) ? SCAN_WARM : t0;
    const __half* bt = g_beta_h + ((size_t)(b * KK + k)) * SS + (t0 - warm);

    float sr = 0.0f, si = 0.0f;
    auto step = [&](float v) {
        float gb = dk * v;
        float nr = fmaf(Ac, sr, fmaf(-Bc, si, gb));
        float ni = fmaf(Bc, sr, Ac * si);
        sr = nr; si = ni;
    };

    const uint4* p4 = (const uint4*)bt;
    for (int h = 0; h < warm / 8; h++) {
        float f[8];
        unpack8(__ldg(p4), f);
        p4++;
        #pragma unroll
        for (int i = 0; i < 8; i++) step(f[i]);
    }

    uint4 m0 = __ldg(p4), m1 = __ldg(p4 + 1);
    float f0[8], f1[8];
    unpack8(m0, f0); unpack8(m1, f1);

    #pragma unroll
    for (int i = 0; i < 8; i++) {
        step(f0[i]); sh[i * KK + k] = __float2half(sr);
    }
    #pragma unroll
    for (int i = 0; i < 8; i++) {
        step(f1[i]); sh[(8 + i) * KK + k] = __float2half(sr);
    }
    __syncthreads();

    __half* sp = g_srseq_h + ((size_t)t0 * BB + b) * KK;
    const uint4* s4 = (const uint4*)sh;
    #pragma unroll
    for (int it = 0; it < 2; it++) {
        int i = k + it * KK;
        int t = i >> 4, c = i & 15;
        *(uint4*)(sp + (size_t)t * (BB * KK) + c * 8) = s4[i];
    }

    if (chunk == SCAN_NCH - 1) { srf[b * KK + k] = sr; sif[b * KK + k] = si; }
}

__global__ __launch_bounds__(KK)
void scan_serial(const float* __restrict__ alpha, const float* __restrict__ omega,
                 const float* __restrict__ R,
                 float* __restrict__ srf, float* __restrict__ sif)
{
    if (__ldg(&g_fast) != 0) return;
    const int b = blockIdx.x, k = threadIdx.x;

    bool diag = true;
    for (int i = k; i < KK * KK; i += KK) {
        int r = i / KK, c = i - r * KK;
        if (r != c && R[i] != 0.0f) diag = false;
    }
    const bool all_diag = (__syncthreads_and(diag ? 1 : 0) != 0);

    const float mag = 1.0f / (1.0f + expf(-alpha[k]));
    const float dk = R[k * KK + k];
    const float cth = cosf(omega[k]);
    const float sth = sinf(omega[k]);

    const __half* bt = g_beta_h + ((size_t)(b * KK + k)) * SS;
    __half* sp = g_srseq_h + (size_t)b * KK + k;
    float sr = 0.0f, si = 0.0f;

    if (all_diag) {
        const float Ac = dk * mag * cth;
        const float Bc = dk * mag * sth;
        #pragma unroll 4
        for (int t = 0; t < SS; t++) {
            float gb = dk * __half2float(__ldg(bt + t));
            float nr = fmaf(Ac, sr, fmaf(-Bc, si, gb));
            float ni = fmaf(Bc, sr, Ac * si);
            sr = nr; si = ni;
            sp[(size_t)t * (BB * KK)] = __float2half(sr);
        }
    } else {
        __shared__ float nrs[KK], nis[KK];
        for (int t = 0; t < SS; t++) {
            float btv = __half2float(__ldg(bt + t));
            float nr = fmaf(mag * cth, sr, fmaf(-mag * sth, si, btv));
            float ni = mag * fmaf(sr, sth, si * cth);
            nrs[k] = nr; nis[k] = ni;
            __syncthreads();
            float a0 = 0.0f, a1 = 0.0f;
            #pragma unroll 8
            for (int j = 0; j < KK; j++) {
                float rj = R[j * KK + k];
                a0 = fmaf(nrs[j], rj, a0);
                a1 = fmaf(nis[j], rj, a1);
            }
            __syncthreads();
            sr = a0; si = a1;
            sp[(size_t)t * (BB * KK)] = __float2half(sr);
        }
    }
    srf[b * KK + k] = sr;
    sif[b * KK + k] = si;
}

// ============================================================================
// launch
// ============================================================================
extern "C" void kernel_launch(void* const* d_in, const int* in_sizes, int n_in,
                              void* d_out, int out_size)
{
    const float* x     = (const float*)d_in[0];
    const float* alpha = (const float*)d_in[1];
    const float* omega = (const float*)d_in[2];
    const float* W_in  = (const float*)d_in[3];
    const float* R     = (const float*)d_in[4];
    const float* W_out = (const float*)d_in[5];
    const float* b_out = (const float*)d_in[6];
    const float* ln_g  = (const float*)d_in[7];
    const float* ln_b  = (const float*)d_in[8];

    float* out = (float*)d_out;                   // (B,S,D)
    float* srf = out + (size_t)BB * SS * DD;      // (B,K)
    float* sif = srf + (size_t)BB * KK;           // (B,K)

    __half* winh_p;  cudaGetSymbolAddress((void**)&winh_p,  g_win_h);
    __half* wouth_p; cudaGetSymbolAddress((void**)&wouth_p, g_wout_h);
    __half* srh_p;   cudaGetSymbolAddress((void**)&srh_p,   g_srseq_h);

    const int SMEM1 = (2 * ASTG_U + 3 * BSTG_U) * (int)sizeof(uint32_t);  // 51200 B
    const int SMEM3 = (A_U + 2 * B_U + Y_U) * (int)sizeof(uint32_t);      // 219136 B
    cudaFuncSetAttribute(gemm_beta, cudaFuncAttributeMaxDynamicSharedMemorySize, SMEM1);
    cudaFuncSetAttribute(gemm_hy,   cudaFuncAttributeMaxDynamicSharedMemorySize, SMEM3);
    cudaFuncSetAttribute(gemm_beta, cudaFuncAttributePreferredSharedMemoryCarveout, 100);
    cudaFuncSetAttribute(gemm_hy,   cudaFuncAttributePreferredSharedMemoryCarveout, 100);

    // 0) fused setup: W_in/W_out -> fp16, fast-path guard
    setup<<<2 * (KK * DD) / 256 + 1, 256>>>(W_in, W_out, R, alpha, winh_p, wouth_p);

    // 1) beta^T = fp16( (x @ W_in^T)^T ) -> g_beta_h (B,K,S)
    gemm_beta<<<dim3(1, MM / 128), 256, SMEM1>>>(x, winh_p);

    // 2) scan (flag-guarded fast path + exact fallback)
    scan_par<<<dim3(SCAN_NCH, BB), KK>>>(alpha, omega, R, srf, sif);
    scan_serial<<<BB, KK>>>(alpha, omega, R, srf, sif);

    // 3+4) FUSED: y = sr_seq @ W_out^T + b_out, LayerNorm, transpose -> out
    gemm_hy<<<MM / 64, 256, SMEM3>>>(srh_p, wouth_p, b_out, ln_g, ln_b, out);
}